// round 13
// baseline (speedup 1.0000x reference)
#include <cuda_runtime.h>
#include <cuda_fp16.h>
#include <math.h>
#include <stdint.h>

static constexpr int BB = 64;
static constexpr int LL = 2048;
static constexpr int HH = 256;
static constexpr int VV = 32000;
static constexpr int TT = LL - 1;
static constexpr float BETA = 0.9f;
static constexpr float OMB  = 0.1f;
static constexpr int CH = 32;

// ---------------- scratch ----------------
__device__ float  g_h [(size_t)BB*LL*HH];       // x = e + ffn (UN-normalized)
__device__ __half g_af[(size_t)BB*LL*HH];
__device__ __half g_ff[(size_t)BB*LL*2*HH];
__device__ __half g_w1t[512*256];
__device__ __half g_w2t[256*512];
__device__ float  g_M [(size_t)BB*HH*HH];
__device__ float  g_y [BB*HH];
__device__ float  g_y2[BB*HH];

#define SWZ(o)  ((o) ^ (((o) >> 3) & 0x70))
#define SWZ5(o) ((o) ^ (((o) >> 5) & 0x70))

__device__ __forceinline__ uint32_t smem_u32(const void* p) {
    uint32_t a;
    asm("{ .reg .u64 t; cvta.to.shared.u64 t, %1; cvt.u32.u64 %0, t; }" : "=r"(a) : "l"(p));
    return a;
}
__device__ __forceinline__ uint32_t packh2(float a, float b) {
    __half2 t = __floats2half2_rn(a, b);
    return *reinterpret_cast<uint32_t*>(&t);
}
__device__ __forceinline__ void ldsm_x4(uint32_t* r, uint32_t addr) {
    asm volatile("ldmatrix.sync.aligned.m8n8.x4.shared.b16 {%0,%1,%2,%3}, [%4];"
        : "=r"(r[0]), "=r"(r[1]), "=r"(r[2]), "=r"(r[3]) : "r"(addr));
}
__device__ __forceinline__ void ldsm_x4t(uint32_t* r, uint32_t addr) {
    asm volatile("ldmatrix.sync.aligned.m8n8.x4.trans.shared.b16 {%0,%1,%2,%3}, [%4];"
        : "=r"(r[0]), "=r"(r[1]), "=r"(r[2]), "=r"(r[3]) : "r"(addr));
}
__device__ __forceinline__ void ldsm_x2(uint32_t* r, uint32_t addr) {
    asm volatile("ldmatrix.sync.aligned.m8n8.x2.shared.b16 {%0,%1}, [%2];"
        : "=r"(r[0]), "=r"(r[1]) : "r"(addr));
}
__device__ __forceinline__ void mma_f16(float* d, const uint32_t* a, uint32_t b0, uint32_t b1) {
    asm volatile("mma.sync.aligned.m16n8k16.row.col.f32.f16.f16.f32 "
        "{%0,%1,%2,%3}, {%4,%5,%6,%7}, {%8,%9}, {%0,%1,%2,%3};"
        : "+f"(d[0]), "+f"(d[1]), "+f"(d[2]), "+f"(d[3])
        : "r"(a[0]), "r"(a[1]), "r"(a[2]), "r"(a[3]), "r"(b0), "r"(b1));
}

#define MBAR_INIT(a, cnt) \
    asm volatile("mbarrier.init.shared.b64 [%0], %1;" :: "r"((uint32_t)(a)), "r"((uint32_t)(cnt)) : "memory")
#define MBAR_TX(a, bytes) \
    asm volatile("mbarrier.arrive.expect_tx.shared.b64 _, [%0], %1;" :: "r"((uint32_t)(a)), "r"((uint32_t)(bytes)) : "memory")
#define BULK(dst, src, bytes, mbar) \
    asm volatile("cp.async.bulk.shared::cta.global.mbarrier::complete_tx::bytes [%0], [%1], %2, [%3];" \
        :: "r"((uint32_t)(dst)), "l"(src), "r"((uint32_t)(bytes)), "r"((uint32_t)(mbar)) : "memory")
#define MBAR_WAIT(a, par) do {                                                    \
    uint32_t _m = (uint32_t)(a); uint32_t _p = (uint32_t)(par); uint32_t _d;      \
    asm volatile("{\n\t.reg .pred p;\n\t"                                         \
        "mbarrier.try_wait.parity.acquire.cta.shared::cta.b64 p, [%1], %2;\n\t"   \
        "selp.b32 %0, 1, 0, p;\n\t}"                                              \
        : "=r"(_d) : "r"(_m), "r"(_p) : "memory");                                \
    if (!_d) {                                                                    \
        asm volatile("{\n\t.reg .pred P1;\n\t"                                    \
            "WL_%=:\n\t"                                                          \
            "mbarrier.try_wait.parity.acquire.cta.shared::cta.b64 P1, [%0], %1, 0x989680;\n\t" \
            "@P1 bra.uni WD_%=;\n\t"                                              \
            "bra.uni WL_%=;\n\t"                                                  \
            "WD_%=:\n\t}"                                                         \
            :: "r"(_m), "r"(_p) : "memory");                                      \
    }                                                                             \
} while (0)

// ---------------- 0a. weights -> fp16, tiled-swizzled 16KB tiles ----------------
__global__ void k_prep(const float* __restrict__ W1, const float* __restrict__ W2) {
    int idx = blockIdx.x * blockDim.x + threadIdx.x;
    {
        int n = idx >> 8, k = idx & 255;
        __half v = __float2half_rn(W1[k * 512 + n]);
        size_t off = (((size_t)(n >> 7) * 4 + (k >> 6)) << 14)
                   + SWZ((uint32_t)((n & 127) * 128 + (k & 63) * 2));
        *(__half*)((char*)g_w1t + off) = v;
    }
    {
        int n = idx >> 9, k = idx & 511;
        __half v = __float2half_rn(W2[k * 256 + n]);
        size_t off = (((size_t)(n >> 7) * 8 + (k >> 6)) << 14)
                   + SWZ((uint32_t)((n & 127) * 128 + (k & 63) * 2));
        *(__half*)((char*)g_w2t + off) = v;
    }
}

// ---------------- 0b. gather -> fp16 tiled-swizzled ----------------
__global__ void k_split(const int* __restrict__ seq, const float* __restrict__ embed) {
    size_t idx = (size_t)blockIdx.x * blockDim.x + threadIdx.x;
    int row = (int)(idx >> 5), g = (int)(idx & 31);
    int tok = seq[row];
    const float4* src = (const float4*)(embed + (size_t)tok * HH + g * 8);
    float4 v0 = src[0], v1 = src[1];
    uint4 o = make_uint4(packh2(v0.x, v0.y), packh2(v0.z, v0.w),
                         packh2(v1.x, v1.y), packh2(v1.z, v1.w));
    int mt = row >> 7, c = g >> 3;
    size_t off = (((size_t)mt * 4 + c) << 14)
               + SWZ((uint32_t)((row & 127) * 128 + (g & 7) * 16));
    *(uint4*)((char*)g_af + off) = o;
}

// ---------------- 1+2. FFN: fp16 HMMA + cp.async.bulk 2-stage ----------------
static constexpr int FFN_SMEM = 1024 + 65536 + 64;

__device__ __forceinline__ void ffn_compute(uint32_t aB, uint32_t bB,
                                            int wm, int wn, int lid, float (&acc)[4][4][4])
{
    #pragma unroll
    for (int ks = 0; ks < 4; ++ks) {
        uint32_t colA = ks * 32 + ((lid >> 4) << 4);
        uint32_t ah[4][4];
        #pragma unroll
        for (int mf = 0; mf < 4; ++mf) {
            uint32_t row = wm * 64 + mf * 16 + (lid & 15);
            ldsm_x4(ah[mf], aB + SWZ(row * 128 + colA));
        }
        uint32_t bh[2][4];
        #pragma unroll
        for (int nf = 0; nf < 2; ++nf) {
            uint32_t row = wn * 32 + nf * 16 + ((lid >> 4) << 3) + (lid & 7);
            uint32_t colB = ks * 32 + (((lid >> 3) & 1) << 4);
            ldsm_x4(bh[nf], bB + SWZ(row * 128 + colB));
        }
        #pragma unroll
        for (int mf = 0; mf < 4; ++mf)
            #pragma unroll
            for (int nf = 0; nf < 2; ++nf)
                #pragma unroll
                for (int j = 0; j < 2; ++j)
                    mma_f16(acc[mf][nf*2+j], ah[mf], bh[nf][j*2], bh[nf][j*2+1]);
    }
}

template<int PHASE>
__global__ __launch_bounds__(256, 2) void k_ffn(
    const int* __restrict__ seq, const float* __restrict__ embed,
    const float* __restrict__ bias)
{
    constexpr int NC = (PHASE == 1) ? 4 : 8;

    extern __shared__ char sm[];
    int*   sseq  = (int*)sm;
    float* sbias = (float*)(sm + 512);
    const uint32_t sb = smem_u32(sm);
    const uint32_t st0 = sb + 1024, st1 = sb + 1024 + 32768;
    const uint32_t mb  = sb + 1024 + 65536;

    const int tid = threadIdx.x, wid = tid >> 5, lid = tid & 31;
    const int wm = wid & 1, wn = wid >> 1;
    const int mt = blockIdx.y, nb0 = blockIdx.x * 128;

    const char* Atl = (const char*)((PHASE == 1) ? (const void*)g_af : (const void*)g_ff)
                    + (((size_t)mt * NC) << 14);
    const char* Btl = (const char*)((PHASE == 1) ? (const void*)g_w1t : (const void*)g_w2t)
                    + (((size_t)blockIdx.x * NC) << 14);

    if (tid < 128) {
        sbias[tid] = bias[nb0 + tid];
        if (PHASE == 2) sseq[tid] = seq[mt * 128 + tid];
    }
    if (tid == 0) { MBAR_INIT(mb, 1); MBAR_INIT(mb + 8, 1); }
    __syncthreads();

    if (tid == 0) {
        MBAR_TX(mb, 32768);
        BULK(st0, Atl, 16384, mb);
        BULK(st0 + 16384, Btl, 16384, mb);
        MBAR_TX(mb + 8, 32768);
        BULK(st1, Atl + 16384, 16384, mb + 8);
        BULK(st1 + 16384, Btl + 16384, 16384, mb + 8);
    }

    float acc[4][4][4];
    #pragma unroll
    for (int a = 0; a < 4; ++a)
        #pragma unroll
        for (int b = 0; b < 4; ++b)
            #pragma unroll
            for (int c = 0; c < 4; ++c) acc[a][b][c] = 0.f;

    for (int c = 0; c < NC; ++c) {
        int s = c & 1;
        uint32_t stg = s ? st1 : st0;
        MBAR_WAIT(mb + s * 8, (c >> 1) & 1);
        ffn_compute(stg, stg + 16384, wm, wn, lid, acc);
        __syncthreads();
        if (tid == 0 && c + 2 < NC) {
            MBAR_TX(mb + s * 8, 32768);
            BULK(stg, Atl + ((size_t)(c + 2) << 14), 16384, mb + s * 8);
            BULK(stg + 16384, Btl + ((size_t)(c + 2) << 14), 16384, mb + s * 8);
        }
    }

    const int qm = lid >> 2, qn = (lid & 3) * 2;
    if (PHASE == 1) {
        uint32_t* SH = (uint32_t*)(sm + 1024);
        #pragma unroll
        for (int mf = 0; mf < 4; ++mf)
            #pragma unroll
            for (int nf = 0; nf < 2; ++nf)
                #pragma unroll
                for (int j = 0; j < 2; ++j) {
                    const float* d = acc[mf][nf*2+j];
                    int nl = wn * 32 + nf * 16 + j * 8 + qn;
                    #pragma unroll
                    for (int hh = 0; hh < 2; ++hh) {
                        int ml = wm * 64 + mf * 16 + qm + hh * 8;
                        float v0 = fmaxf(d[hh*2+0] + sbias[nl],   0.f);
                        float v1 = fmaxf(d[hh*2+1] + sbias[nl+1], 0.f);
                        SH[ml * 64 + (nl >> 1)] = packh2(v0, v1);
                    }
                }
        __syncthreads();
        char* gff = (char*)g_ff;
        #pragma unroll
        for (int t = 0; t < 8; ++t) {
            int idx = t * 256 + tid;
            int tile = idx >> 10, rem = idx & 1023;
            int r = rem >> 3, j = rem & 7;
            uint4 v = ((const uint4*)SH)[r * 16 + tile * 8 + j];
            size_t off = (((size_t)mt * 8 + blockIdx.x * 2 + tile) << 14)
                       + SWZ((uint32_t)(r * 128 + j * 16));
            *(uint4*)(gff + off) = v;
        }
    } else {
        float* SF = (float*)(sm + 1024);
        #pragma unroll
        for (int mf = 0; mf < 4; ++mf)
            #pragma unroll
            for (int nf = 0; nf < 2; ++nf)
                #pragma unroll
                for (int j = 0; j < 2; ++j) {
                    const float* d = acc[mf][nf*2+j];
                    int nl = wn * 32 + nf * 16 + j * 8 + qn;
                    #pragma unroll
                    for (int hh = 0; hh < 2; ++hh) {
                        int ml = wm * 64 + mf * 16 + qm + hh * 8;
                        SF[ml * 128 + nl]     = d[hh*2+0] + sbias[nl];
                        SF[ml * 128 + nl + 1] = d[hh*2+1] + sbias[nl+1];
                    }
                }
        __syncthreads();
        int row = tid >> 1, part = tid & 1;
        int tok = sseq[row];
        const float4* ep = (const float4*)(embed + (size_t)tok * HH + nb0);
        const float4* sfp = (const float4*)(SF + row * 128);
        float4* gp = (float4*)(g_h + ((size_t)mt * 128 + row) * HH + nb0);
        #pragma unroll
        for (int j = 0; j < 16; ++j) {
            int c4 = part * 16 + j;
            float4 f = sfp[c4];
            float4 e = ep[c4];
            f.x += e.x; f.y += e.y; f.z += e.z; f.w += e.w;
            gp[c4] = f;
        }
    }
}

// ---------------- 3. scan: fp16 HMMA chunked delta rule, LN fused (2-pass loader) ----------------
static constexpr uint32_t OFF_MH  = 0;        // [128][512B] fp16 swz5
static constexpr uint32_t OFF_KH  = 65536;    // [32][512B] fp16 swz5
static constexpr uint32_t OFF_KF  = 81920;    // [32][256] fp32 normalized K
static constexpr uint32_t OFF_SD  = 114688;   // [32][128] f32 raw U
static constexpr uint32_t OFF_DT  = 131072;   // [128][80B] fp16 weighted d^T
static constexpr uint32_t OFF_G   = 141312;   // [32][36] f32
static constexpr uint32_t OFF_A   = 145920;   // [32][32] f32
static constexpr uint32_t OFF_SC  = 150016;   // sc[32], ct[32], wv[32], spw[33] (1024B reserved)
static constexpr uint32_t OFF_GB  = 151040;   // gamma[256], beta[256]
static constexpr int SCAN_SMEM_BYTES = 153088;

__global__ __launch_bounds__(256, 1) void k_scan(
    const float* __restrict__ gamma, const float* __restrict__ beta_ln)
{
    extern __shared__ char smc[];
    const uint32_t sb = smem_u32(smc);
    const uint32_t MH = sb + OFF_MH;
    const uint32_t KH = sb + OFF_KH;
    float* sKF = (float*)(smc + OFF_KF);
    float* sD  = (float*)(smc + OFF_SD);
    float* sG  = (float*)(smc + OFF_G);
    float* sA  = (float*)(smc + OFF_A);
    float* sc  = (float*)(smc + OFF_SC);
    float* ct  = sc + 32;
    float* wv  = ct + 32;
    float* spw = wv + 32;
    float* sGam = (float*)(smc + OFF_GB);
    float* sBet = sGam + 256;

    const int tid = threadIdx.x, wid = tid >> 5, lid = tid & 31;
    const int qm = lid >> 2, qn = (lid & 3) * 2;
    const int b  = blockIdx.x >> 1;
    const int r0 = (blockIdx.x & 1) * 128;
    const float* hb = g_h + (size_t)b * LL * HH;

    for (int i = tid; i < 65536 / 16; i += 256)
        ((uint4*)(smc + OFF_MH))[i] = make_uint4(0, 0, 0, 0);
    sGam[tid] = gamma[tid];
    sBet[tid] = beta_ln[tid];
    if (tid == 0) {
        spw[0] = 1.f;
        for (int i = 1; i <= CH; ++i) spw[i] = spw[i-1] * BETA;
    }
    __syncthreads();

    float acc[32][4];
    #pragma unroll
    for (int f = 0; f < 32; ++f)
        #pragma unroll
        for (int q = 0; q < 4; ++q) acc[f][q] = 0.f;

    const int klt = tid >> 3, kq = tid & 7;

    for (int t0 = 0; t0 < TT; t0 += CH) {
        const int Cc = min(CH, TT - t0);
        __syncthreads();

        // ---- (a) fused LN, two-pass (low register): pass1 stats, pass2 normalize+store ----
        {
            const float4* src = (const float4*)(hb + (size_t)(t0 + klt) * HH + kq * 32);
            const bool pad = (klt >= Cc);
            float s = 0.f, sq = 0.f;
            if (!pad) {
                #pragma unroll
                for (int g = 0; g < 8; ++g) {
                    float4 v = src[g];
                    s  += v.x + v.y + v.z + v.w;
                    sq += v.x*v.x + v.y*v.y + v.z*v.z + v.w*v.w;
                }
            }
            #pragma unroll
            for (int o = 1; o < 8; o <<= 1) {
                s  += __shfl_xor_sync(0xffffffffu, s, o);
                sq += __shfl_xor_sync(0xffffffffu, sq, o);
            }
            float mu  = s * (1.0f / HH);
            float inv = rsqrtf(sq * (1.0f / HH) - mu * mu + 1e-5f);
            float4* kf = (float4*)(sKF + klt * 256 + kq * 32);
            #pragma unroll
            for (int g = 0; g < 4; ++g) {
                float f[8];
                if (pad) {
                    #pragma unroll
                    for (int q = 0; q < 8; ++q) f[q] = 0.f;
                } else {
                    float4 v0 = src[2*g], v1 = src[2*g + 1];   // L1 hit (pass 2)
                    int col = kq * 32 + g * 8;
                    f[0] = (v0.x-mu)*inv*sGam[col+0] + sBet[col+0];
                    f[1] = (v0.y-mu)*inv*sGam[col+1] + sBet[col+1];
                    f[2] = (v0.z-mu)*inv*sGam[col+2] + sBet[col+2];
                    f[3] = (v0.w-mu)*inv*sGam[col+3] + sBet[col+3];
                    f[4] = (v1.x-mu)*inv*sGam[col+4] + sBet[col+4];
                    f[5] = (v1.y-mu)*inv*sGam[col+5] + sBet[col+5];
                    f[6] = (v1.z-mu)*inv*sGam[col+6] + sBet[col+6];
                    f[7] = (v1.w-mu)*inv*sGam[col+7] + sBet[col+7];
                }
                kf[2*g]     = make_float4(f[0], f[1], f[2], f[3]);
                kf[2*g + 1] = make_float4(f[4], f[5], f[6], f[7]);
                uint32_t off = SWZ5((uint32_t)(klt * 512 + (kq * 32 + g * 8) * 2));
                *(uint4*)(smc + OFF_KH + off) =
                    make_uint4(packh2(f[0], f[1]), packh2(f[2], f[3]),
                               packh2(f[4], f[5]), packh2(f[6], f[7]));
            }
        }
        __syncthreads();

        // ---- (b) Gram G = K K^T ----
        {
            float gacc[4] = {0.f, 0.f, 0.f, 0.f};
            const int mh = wid & 1, nq = wid >> 1;
            const uint32_t arow = (uint32_t)(16 * mh + (lid & 15)) * 512;
            const uint32_t asel = (uint32_t)((lid >> 4) << 4);
            const uint32_t brow = (uint32_t)(8 * nq + (lid & 7)) * 512;
            const uint32_t bsel = (uint32_t)(((lid >> 3) & 1) << 4);
            #pragma unroll
            for (int ks = 0; ks < 16; ++ks) {
                uint32_t ca = ks * 32;
                uint32_t ag[4], gb[2];
                ldsm_x4(ag, KH + SWZ5(arow + ca + asel));
                ldsm_x2(gb, KH + SWZ5(brow + ca + bsel));
                mma_f16(gacc, ag, gb[0], gb[1]);
            }
            int t = 16 * mh + qm, s = 8 * nq + qn;
            sG[t*36 + s] = gacc[0]; sG[t*36 + s + 1] = gacc[1];
            sG[(t+8)*36 + s] = gacc[2]; sG[(t+8)*36 + s + 1] = gacc[3];
        }
        __syncthreads();

        if (tid < 32) {
            float g = sG[tid*36 + tid];
            float s = 1.0f / (g + 1e-6f);
            sc[tid] = s;
            ct[tid] = s * spw[tid];
            wv[tid] = (tid < Cc) ? OMB * spw[Cc - 1 - tid] : 0.f;
        }
        __syncthreads();

        // ---- (c) coupling coefs + (d) U = M K^T ----
        for (int p = tid; p < 1024; p += 256) {
            int t = p >> 5, s = p & 31;
            if (s < t) sA[p] = sG[t*36 + s] * sc[t] * OMB * spw[t - 1 - s];
        }
        {
            float uacc[4][4];
            #pragma unroll
            for (int f = 0; f < 4; ++f)
                #pragma unroll
                for (int q = 0; q < 4; ++q) uacc[f][q] = 0.f;
            const uint32_t mrow = (uint32_t)(16 * wid + (lid & 15)) * 512;
            const uint32_t asel = (uint32_t)((lid >> 4) << 4);
            const uint32_t brow0 = (uint32_t)(((lid >> 4) << 3) + (lid & 7)) * 512;
            const uint32_t brow1 = brow0 + 16 * 512;
            const uint32_t bsel = (uint32_t)(((lid >> 3) & 1) << 4);
            #pragma unroll
            for (int ks = 0; ks < 16; ++ks) {
                uint32_t ca = ks * 32;
                uint32_t am[4], b0[4], b1[4];
                ldsm_x4(am, MH + SWZ5(mrow + ca + asel));
                ldsm_x4(b0, KH + SWZ5(brow0 + ca + bsel));
                ldsm_x4(b1, KH + SWZ5(brow1 + ca + bsel));
                #pragma unroll
                for (int f = 0; f < 4; ++f) {
                    const uint32_t* bh = (f < 2) ? b0 : b1;
                    int j = (f & 1) * 2;
                    mma_f16(uacc[f], am, bh[j], bh[j+1]);
                }
            }
            int i = 16 * wid + qm;
            #pragma unroll
            for (int f = 0; f < 4; ++f) {
                int lt = 8 * f + qn;
                sD[lt*128 + i]           = uacc[f][0];
                sD[(lt+1)*128 + i]       = uacc[f][1];
                sD[lt*128 + i + 8]       = uacc[f][2];
                sD[(lt+1)*128 + i + 8]   = uacc[f][3];
            }
        }
        __syncthreads();

        // ---- (e) triangular solve; rhs from fp32 smem sKF ----
        if (tid < 128) {
            const int i = tid;
            float d[CH];
            #pragma unroll
            for (int t = 0; t < CH; ++t)
                d[t] = sKF[t * 256 + r0 + i] - ct[t] * sD[t*128 + i];
            #pragma unroll
            for (int s = 0; s < CH - 1; ++s)
                #pragma unroll
                for (int t = s + 1; t < CH; ++t)
                    d[t] -= sA[t*32 + s] * d[s];
            #pragma unroll
            for (int s = 0; s < CH; s += 2)
                *(uint32_t*)(smc + OFF_DT + i*80 + s*2) =
                    packh2(d[s] * wv[s], d[s+1] * wv[s+1]);
        }
        __syncthreads();

        // ---- (f) M update: acc = beta^Cc * acc + dT^T @ K ----
        {
            float bc = spw[Cc];
            #pragma unroll
            for (int f = 0; f < 32; ++f)
                #pragma unroll
                for (int q = 0; q < 4; ++q) acc[f][q] *= bc;
            const uint32_t adbase = (uint32_t)(16 * wid + (lid & 15)) * 80
                                  + (uint32_t)((lid >> 4) << 4);
            const uint32_t tsel = (uint32_t)((lid >> 4) << 3) * 2;
            #pragma unroll
            for (int ks = 0; ks < 2; ++ks) {
                uint32_t ad[4];
                ldsm_x4(ad, sb + OFF_DT + adbase + ks * 32);
                uint32_t trow = (uint32_t)(ks * 16 + (lid & 15)) * 512;
                #pragma unroll
                for (int jg = 0; jg < 16; ++jg) {
                    uint32_t o = SWZ5(trow + jg * 32 + tsel);
                    uint32_t bt[4];
                    ldsm_x4t(bt, KH + o);
                    mma_f16(acc[jg*2],   ad, bt[0], bt[1]);
                    mma_f16(acc[jg*2+1], ad, bt[2], bt[3]);
                }
            }
        }

        // ---- (g) publish M fp16 for next chunk ----
        if (t0 + CH < TT) {
            int r1 = 16 * wid + qm;
            #pragma unroll
            for (int f = 0; f < 32; ++f) {
                int c = f * 8 + qn;
                *(uint32_t*)(smc + OFF_MH + SWZ5((uint32_t)(r1 * 512 + c * 2))) =
                    packh2(acc[f][0], acc[f][1]);
                *(uint32_t*)(smc + OFF_MH + SWZ5((uint32_t)((r1 + 8) * 512 + c * 2))) =
                    packh2(acc[f][2], acc[f][3]);
            }
        }
    }

    // ---- final: stage fp32 M, write g_M ----
    __syncthreads();
    {
        float* SF = (float*)smc;
        int r1 = 16 * wid + qm;
        #pragma unroll
        for (int f = 0; f < 32; ++f) {
            int c = f * 8 + qn;
            SF[r1*256 + c]       = acc[f][0];
            SF[r1*256 + c + 1]   = acc[f][1];
            SF[(r1+8)*256 + c]   = acc[f][2];
            SF[(r1+8)*256 + c+1] = acc[f][3];
        }
        __syncthreads();
        const float4* sp = (const float4*)SF;
        for (int q = tid; q < 128 * 64; q += 256) {
            int i = q >> 6, j4 = q & 63;
            ((float4*)(g_M + ((size_t)b * HH + r0 + i) * HH))[j4] = sp[i*64 + j4];
        }
    }
}

// ---------------- 5. readout: y = M LN(h_last) ----------------
__global__ void k_read1(const float* __restrict__ gamma, const float* __restrict__ beta_ln) {
    int b = blockIdx.x;
    int tid = threadIdx.x;
    __shared__ float hl[HH];
    __shared__ float red[8];
    float x = g_h[((size_t)b * LL + (LL - 1)) * HH + tid];
    float s = x;
    #pragma unroll
    for (int o = 16; o; o >>= 1) s += __shfl_xor_sync(0xffffffffu, s, o);
    if ((tid & 31) == 0) red[tid >> 5] = s;
    __syncthreads();
    float mu = 0.f;
    #pragma unroll
    for (int i = 0; i < 8; ++i) mu += red[i];
    mu *= (1.0f / HH);
    __syncthreads();
    float dx = x - mu;
    float v = dx * dx;
    #pragma unroll
    for (int o = 16; o; o >>= 1) v += __shfl_xor_sync(0xffffffffu, v, o);
    if ((tid & 31) == 0) red[tid >> 5] = v;
    __syncthreads();
    float var = 0.f;
    #pragma unroll
    for (int i = 0; i < 8; ++i) var += red[i];
    var *= (1.0f / HH);
    hl[tid] = dx * rsqrtf(var + 1e-5f) * gamma[tid] + beta_ln[tid];
    __syncthreads();
    int w = tid >> 5, lane = tid & 31;
    for (int i = w; i < HH; i += 8) {
        const float* Mr = g_M + ((size_t)b * HH + i) * HH;
        float acc = 0.f;
        #pragma unroll
        for (int j = lane; j < HH; j += 32) acc += Mr[j] * hl[j];
        #pragma unroll
        for (int o = 16; o; o >>= 1) acc += __shfl_xor_sync(0xffffffffu, acc, o);
        if (lane == 0) g_y[b * HH + i] = acc;
    }
}

__global__ void k_read2(const float* __restrict__ rp_W, const float* __restrict__ rp_b) {
    int b = blockIdx.x, n = threadIdx.x;
    __shared__ float ys[HH];
    ys[n] = g_y[b * HH + n];
    __syncthreads();
    float acc = rp_b[n];
    #pragma unroll 4
    for (int k = 0; k < HH; ++k) acc += ys[k] * rp_W[k * HH + n];
    g_y2[b * HH + n] = acc;
}

static constexpr int OUT_SMEM_BYTES = (HH * 128 + BB * 257) * 4;

__global__ __launch_bounds__(256) void k_out(
    const float* __restrict__ out_W, const float* __restrict__ out_b,
    float* __restrict__ out)
{
    extern __shared__ float smf[];
    float* sW  = smf;
    float* sy2 = smf + HH * 128;
    int tid = threadIdx.x;
    int n_base = blockIdx.x * 128;

    for (int idx = tid; idx < HH * 32; idx += 256) {
        int k = idx >> 5, q = idx & 31;
        *(float4*)(sW + k*128 + q*4) = *(const float4*)(out_W + (size_t)k * VV + n_base + q*4);
    }
    for (int idx = tid; idx < BB * 64; idx += 256) {
        int bb = idx >> 6, q = idx & 63;
        float4 v = *(const float4*)(g_y2 + bb * HH + q*4);
        float* d = sy2 + bb*257 + q*4;
        d[0] = v.x; d[1] = v.y; d[2] = v.z; d[3] = v.w;
    }
    __syncthreads();

    int bg = tid >> 4, ng = tid & 15;
    int b0 = bg * 4, n0 = ng * 8;
    float acc[4][8];
    #pragma unroll
    for (int r = 0; r < 4; ++r)
        #pragma unroll
        for (int c = 0; c < 8; ++c) acc[r][c] = 0.f;
    for (int k = 0; k < HH; ++k) {
        float4 w0 = *(const float4*)(sW + k*128 + n0);
        float4 w1 = *(const float4*)(sW + k*128 + n0 + 4);
        float wv[8] = {w0.x, w0.y, w0.z, w0.w, w1.x, w1.y, w1.z, w1.w};
        #pragma unroll
        for (int r = 0; r < 4; ++r) {
            float yv = sy2[(b0+r)*257 + k];
            #pragma unroll
            for (int c = 0; c < 8; ++c) acc[r][c] += yv * wv[c];
        }
    }
    #pragma unroll
    for (int r = 0; r < 4; ++r)
        #pragma unroll
        for (int c = 0; c < 8; ++c)
            out[(size_t)(b0+r) * VV + n_base + n0 + c] = acc[r][c] + out_b[n_base + n0 + c];
}

// ---------------- launch ----------------
extern "C" void kernel_launch(void* const* d_in, const int* in_sizes, int n_in,
                              void* d_out, int out_size) {
    (void)in_sizes; (void)n_in; (void)out_size;
    const int*   seq     = (const int*)  d_in[0];
    const float* embed   = (const float*)d_in[1];
    const float* W1      = (const float*)d_in[2];
    const float* b1      = (const float*)d_in[3];
    const float* W2      = (const float*)d_in[4];
    const float* b2      = (const float*)d_in[5];
    const float* gamma   = (const float*)d_in[6];
    const float* beta_ln = (const float*)d_in[7];
    const float* rp_W    = (const float*)d_in[8];
    const float* rp_b    = (const float*)d_in[9];
    const float* out_W   = (const float*)d_in[10];
    const float* out_b   = (const float*)d_in[11];
    float* out = (float*)d_out;

    cudaFuncSetAttribute(k_ffn<1>, cudaFuncAttributeMaxDynamicSharedMemorySize, FFN_SMEM);
    cudaFuncSetAttribute(k_ffn<2>, cudaFuncAttributeMaxDynamicSharedMemorySize, FFN_SMEM);
    cudaFuncSetAttribute(k_scan,   cudaFuncAttributeMaxDynamicSharedMemorySize, SCAN_SMEM_BYTES);
    cudaFuncSetAttribute(k_out,    cudaFuncAttributeMaxDynamicSharedMemorySize, OUT_SMEM_BYTES);

    k_prep<<<512, 256>>>(W1, W2);
    k_split<<<BB * LL * 32 / 256, 256>>>(seq, embed);
    k_ffn<1><<<dim3(4, BB*LL/128), 256, FFN_SMEM>>>(seq, embed, b1);
    k_ffn<2><<<dim3(2, BB*LL/128), 256, FFN_SMEM>>>(seq, embed, b2);
    k_scan<<<BB * 2, 256, SCAN_SMEM_BYTES>>>(gamma, beta_ln);
    k_read1<<<BB, HH>>>(gamma, beta_ln);
    k_read2<<<BB, HH>>>(rp_W, rp_b);
    k_out<<<VV / 128, 256, OUT_SMEM_BYTES>>>(out_W, out_b, out);
}

// round 14
// speedup vs baseline: 1.1735x; 1.1735x over previous
#include <cuda_runtime.h>
#include <cuda_fp16.h>
#include <math.h>
#include <stdint.h>

static constexpr int BB = 64;
static constexpr int LL = 2048;
static constexpr int HH = 256;
static constexpr int VV = 32000;
static constexpr int TT = LL - 1;
static constexpr float BETA = 0.9f;
static constexpr float OMB  = 0.1f;
static constexpr int CH = 32;

// ---------------- scratch ----------------
__device__ float  g_h [(size_t)BB*LL*HH];       // x = e + ffn (UN-normalized)
__device__ __half g_af[(size_t)BB*LL*HH];
__device__ __half g_ff[(size_t)BB*LL*2*HH];
__device__ __half g_w1t[512*256];
__device__ __half g_w2t[256*512];
__device__ float  g_M [(size_t)BB*HH*HH];
__device__ float  g_y [BB*HH];
__device__ float  g_y2[BB*HH];

#define SWZ(o)  ((o) ^ (((o) >> 3) & 0x70))
#define SWZ5(o) ((o) ^ (((o) >> 5) & 0x70))

__device__ __forceinline__ uint32_t smem_u32(const void* p) {
    uint32_t a;
    asm("{ .reg .u64 t; cvta.to.shared.u64 t, %1; cvt.u32.u64 %0, t; }" : "=r"(a) : "l"(p));
    return a;
}
__device__ __forceinline__ uint32_t packh2(float a, float b) {
    __half2 t = __floats2half2_rn(a, b);
    return *reinterpret_cast<uint32_t*>(&t);
}
__device__ __forceinline__ void ldsm_x4(uint32_t* r, uint32_t addr) {
    asm volatile("ldmatrix.sync.aligned.m8n8.x4.shared.b16 {%0,%1,%2,%3}, [%4];"
        : "=r"(r[0]), "=r"(r[1]), "=r"(r[2]), "=r"(r[3]) : "r"(addr));
}
__device__ __forceinline__ void ldsm_x4t(uint32_t* r, uint32_t addr) {
    asm volatile("ldmatrix.sync.aligned.m8n8.x4.trans.shared.b16 {%0,%1,%2,%3}, [%4];"
        : "=r"(r[0]), "=r"(r[1]), "=r"(r[2]), "=r"(r[3]) : "r"(addr));
}
__device__ __forceinline__ void ldsm_x2(uint32_t* r, uint32_t addr) {
    asm volatile("ldmatrix.sync.aligned.m8n8.x2.shared.b16 {%0,%1}, [%2];"
        : "=r"(r[0]), "=r"(r[1]) : "r"(addr));
}
__device__ __forceinline__ void mma_f16(float* d, const uint32_t* a, uint32_t b0, uint32_t b1) {
    asm volatile("mma.sync.aligned.m16n8k16.row.col.f32.f16.f16.f32 "
        "{%0,%1,%2,%3}, {%4,%5,%6,%7}, {%8,%9}, {%0,%1,%2,%3};"
        : "+f"(d[0]), "+f"(d[1]), "+f"(d[2]), "+f"(d[3])
        : "r"(a[0]), "r"(a[1]), "r"(a[2]), "r"(a[3]), "r"(b0), "r"(b1));
}

#define MBAR_INIT(a, cnt) \
    asm volatile("mbarrier.init.shared.b64 [%0], %1;" :: "r"((uint32_t)(a)), "r"((uint32_t)(cnt)) : "memory")
#define MBAR_TX(a, bytes) \
    asm volatile("mbarrier.arrive.expect_tx.shared.b64 _, [%0], %1;" :: "r"((uint32_t)(a)), "r"((uint32_t)(bytes)) : "memory")
#define BULK(dst, src, bytes, mbar) \
    asm volatile("cp.async.bulk.shared::cta.global.mbarrier::complete_tx::bytes [%0], [%1], %2, [%3];" \
        :: "r"((uint32_t)(dst)), "l"(src), "r"((uint32_t)(bytes)), "r"((uint32_t)(mbar)) : "memory")
#define MBAR_WAIT(a, par) do {                                                    \
    uint32_t _m = (uint32_t)(a); uint32_t _p = (uint32_t)(par); uint32_t _d;      \
    asm volatile("{\n\t.reg .pred p;\n\t"                                         \
        "mbarrier.try_wait.parity.acquire.cta.shared::cta.b64 p, [%1], %2;\n\t"   \
        "selp.b32 %0, 1, 0, p;\n\t}"                                              \
        : "=r"(_d) : "r"(_m), "r"(_p) : "memory");                                \
    if (!_d) {                                                                    \
        asm volatile("{\n\t.reg .pred P1;\n\t"                                    \
            "WL_%=:\n\t"                                                          \
            "mbarrier.try_wait.parity.acquire.cta.shared::cta.b64 P1, [%0], %1, 0x989680;\n\t" \
            "@P1 bra.uni WD_%=;\n\t"                                              \
            "bra.uni WL_%=;\n\t"                                                  \
            "WD_%=:\n\t}"                                                         \
            :: "r"(_m), "r"(_p) : "memory");                                      \
    }                                                                             \
} while (0)

// ---------------- 0a. weights -> fp16, tiled-swizzled 16KB tiles ----------------
__global__ void k_prep(const float* __restrict__ W1, const float* __restrict__ W2) {
    int idx = blockIdx.x * blockDim.x + threadIdx.x;
    {
        int n = idx >> 8, k = idx & 255;
        __half v = __float2half_rn(W1[k * 512 + n]);
        size_t off = (((size_t)(n >> 7) * 4 + (k >> 6)) << 14)
                   + SWZ((uint32_t)((n & 127) * 128 + (k & 63) * 2));
        *(__half*)((char*)g_w1t + off) = v;
    }
    {
        int n = idx >> 9, k = idx & 511;
        __half v = __float2half_rn(W2[k * 256 + n]);
        size_t off = (((size_t)(n >> 7) * 8 + (k >> 6)) << 14)
                   + SWZ((uint32_t)((n & 127) * 128 + (k & 63) * 2));
        *(__half*)((char*)g_w2t + off) = v;
    }
}

// ---------------- 0b. gather -> fp16 tiled-swizzled ----------------
__global__ void k_split(const int* __restrict__ seq, const float* __restrict__ embed) {
    size_t idx = (size_t)blockIdx.x * blockDim.x + threadIdx.x;
    int row = (int)(idx >> 5), g = (int)(idx & 31);
    int tok = seq[row];
    const float4* src = (const float4*)(embed + (size_t)tok * HH + g * 8);
    float4 v0 = src[0], v1 = src[1];
    uint4 o = make_uint4(packh2(v0.x, v0.y), packh2(v0.z, v0.w),
                         packh2(v1.x, v1.y), packh2(v1.z, v1.w));
    int mt = row >> 7, c = g >> 3;
    size_t off = (((size_t)mt * 4 + c) << 14)
               + SWZ((uint32_t)((row & 127) * 128 + (g & 7) * 16));
    *(uint4*)((char*)g_af + off) = o;
}

// ---------------- 1+2. FFN: fp16 HMMA + cp.async.bulk 2-stage ----------------
static constexpr int FFN_SMEM = 1024 + 65536 + 64;

__device__ __forceinline__ void ffn_compute(uint32_t aB, uint32_t bB,
                                            int wm, int wn, int lid, float (&acc)[4][4][4])
{
    #pragma unroll
    for (int ks = 0; ks < 4; ++ks) {
        uint32_t colA = ks * 32 + ((lid >> 4) << 4);
        uint32_t ah[4][4];
        #pragma unroll
        for (int mf = 0; mf < 4; ++mf) {
            uint32_t row = wm * 64 + mf * 16 + (lid & 15);
            ldsm_x4(ah[mf], aB + SWZ(row * 128 + colA));
        }
        uint32_t bh[2][4];
        #pragma unroll
        for (int nf = 0; nf < 2; ++nf) {
            uint32_t row = wn * 32 + nf * 16 + ((lid >> 4) << 3) + (lid & 7);
            uint32_t colB = ks * 32 + (((lid >> 3) & 1) << 4);
            ldsm_x4(bh[nf], bB + SWZ(row * 128 + colB));
        }
        #pragma unroll
        for (int mf = 0; mf < 4; ++mf)
            #pragma unroll
            for (int nf = 0; nf < 2; ++nf)
                #pragma unroll
                for (int j = 0; j < 2; ++j)
                    mma_f16(acc[mf][nf*2+j], ah[mf], bh[nf][j*2], bh[nf][j*2+1]);
    }
}

template<int PHASE>
__global__ __launch_bounds__(256, 2) void k_ffn(
    const int* __restrict__ seq, const float* __restrict__ embed,
    const float* __restrict__ bias)
{
    constexpr int NC = (PHASE == 1) ? 4 : 8;

    extern __shared__ char sm[];
    int*   sseq  = (int*)sm;
    float* sbias = (float*)(sm + 512);
    const uint32_t sb = smem_u32(sm);
    const uint32_t st0 = sb + 1024, st1 = sb + 1024 + 32768;
    const uint32_t mb  = sb + 1024 + 65536;

    const int tid = threadIdx.x, wid = tid >> 5, lid = tid & 31;
    const int wm = wid & 1, wn = wid >> 1;
    const int mt = blockIdx.y, nb0 = blockIdx.x * 128;

    const char* Atl = (const char*)((PHASE == 1) ? (const void*)g_af : (const void*)g_ff)
                    + (((size_t)mt * NC) << 14);
    const char* Btl = (const char*)((PHASE == 1) ? (const void*)g_w1t : (const void*)g_w2t)
                    + (((size_t)blockIdx.x * NC) << 14);

    if (tid < 128) {
        sbias[tid] = bias[nb0 + tid];
        if (PHASE == 2) sseq[tid] = seq[mt * 128 + tid];
    }
    if (tid == 0) { MBAR_INIT(mb, 1); MBAR_INIT(mb + 8, 1); }
    __syncthreads();

    if (tid == 0) {
        MBAR_TX(mb, 32768);
        BULK(st0, Atl, 16384, mb);
        BULK(st0 + 16384, Btl, 16384, mb);
        MBAR_TX(mb + 8, 32768);
        BULK(st1, Atl + 16384, 16384, mb + 8);
        BULK(st1 + 16384, Btl + 16384, 16384, mb + 8);
    }

    float acc[4][4][4];
    #pragma unroll
    for (int a = 0; a < 4; ++a)
        #pragma unroll
        for (int b = 0; b < 4; ++b)
            #pragma unroll
            for (int c = 0; c < 4; ++c) acc[a][b][c] = 0.f;

    for (int c = 0; c < NC; ++c) {
        int s = c & 1;
        uint32_t stg = s ? st1 : st0;
        MBAR_WAIT(mb + s * 8, (c >> 1) & 1);
        ffn_compute(stg, stg + 16384, wm, wn, lid, acc);
        __syncthreads();
        if (tid == 0 && c + 2 < NC) {
            MBAR_TX(mb + s * 8, 32768);
            BULK(stg, Atl + ((size_t)(c + 2) << 14), 16384, mb + s * 8);
            BULK(stg + 16384, Btl + ((size_t)(c + 2) << 14), 16384, mb + s * 8);
        }
    }

    const int qm = lid >> 2, qn = (lid & 3) * 2;
    if (PHASE == 1) {
        uint32_t* SH = (uint32_t*)(sm + 1024);
        #pragma unroll
        for (int mf = 0; mf < 4; ++mf)
            #pragma unroll
            for (int nf = 0; nf < 2; ++nf)
                #pragma unroll
                for (int j = 0; j < 2; ++j) {
                    const float* d = acc[mf][nf*2+j];
                    int nl = wn * 32 + nf * 16 + j * 8 + qn;
                    #pragma unroll
                    for (int hh = 0; hh < 2; ++hh) {
                        int ml = wm * 64 + mf * 16 + qm + hh * 8;
                        float v0 = fmaxf(d[hh*2+0] + sbias[nl],   0.f);
                        float v1 = fmaxf(d[hh*2+1] + sbias[nl+1], 0.f);
                        SH[ml * 64 + (nl >> 1)] = packh2(v0, v1);
                    }
                }
        __syncthreads();
        char* gff = (char*)g_ff;
        #pragma unroll
        for (int t = 0; t < 8; ++t) {
            int idx = t * 256 + tid;
            int tile = idx >> 10, rem = idx & 1023;
            int r = rem >> 3, j = rem & 7;
            uint4 v = ((const uint4*)SH)[r * 16 + tile * 8 + j];
            size_t off = (((size_t)mt * 8 + blockIdx.x * 2 + tile) << 14)
                       + SWZ((uint32_t)(r * 128 + j * 16));
            *(uint4*)(gff + off) = v;
        }
    } else {
        float* SF = (float*)(sm + 1024);
        #pragma unroll
        for (int mf = 0; mf < 4; ++mf)
            #pragma unroll
            for (int nf = 0; nf < 2; ++nf)
                #pragma unroll
                for (int j = 0; j < 2; ++j) {
                    const float* d = acc[mf][nf*2+j];
                    int nl = wn * 32 + nf * 16 + j * 8 + qn;
                    #pragma unroll
                    for (int hh = 0; hh < 2; ++hh) {
                        int ml = wm * 64 + mf * 16 + qm + hh * 8;
                        SF[ml * 128 + nl]     = d[hh*2+0] + sbias[nl];
                        SF[ml * 128 + nl + 1] = d[hh*2+1] + sbias[nl+1];
                    }
                }
        __syncthreads();
        int row = tid >> 1, part = tid & 1;
        int tok = sseq[row];
        const float4* ep = (const float4*)(embed + (size_t)tok * HH + nb0);
        const float4* sfp = (const float4*)(SF + row * 128);
        float4* gp = (float4*)(g_h + ((size_t)mt * 128 + row) * HH + nb0);
        #pragma unroll
        for (int j = 0; j < 16; ++j) {
            int c4 = part * 16 + j;
            float4 f = sfp[c4];
            float4 e = ep[c4];
            f.x += e.x; f.y += e.y; f.z += e.z; f.w += e.w;
            gp[c4] = f;
        }
    }
}

// ---------------- 3. scan: fp16 HMMA chunked delta rule, LN fused (conflict-free) ----------------
static constexpr uint32_t OFF_MH  = 0;        // [128][512B] fp16 swz5
static constexpr uint32_t OFF_KH  = 65536;    // [32][512B] fp16 swz5
static constexpr uint32_t OFF_SD  = 81920;    // [32][128] f32 raw U
static constexpr uint32_t OFF_DT  = 98304;    // [128][80B] fp16 weighted d^T
static constexpr uint32_t OFF_G   = 108544;   // [32][36] f32
static constexpr uint32_t OFF_A   = 113152;   // [32][32] f32
static constexpr uint32_t OFF_SC  = 117248;   // sc[32], ct[32], wv[32], spw[33] (1024B)
static constexpr uint32_t OFF_GB  = 118272;   // gammaT[256], betaT[256] (transposed)
static constexpr int SCAN_SMEM_BYTES = 131584; // >= 131072 final staging

__global__ __launch_bounds__(256, 1) void k_scan(
    const float* __restrict__ gamma, const float* __restrict__ beta_ln)
{
    extern __shared__ char smc[];
    const uint32_t sb = smem_u32(smc);
    const uint32_t MH = sb + OFF_MH;
    const uint32_t KH = sb + OFF_KH;
    float* sD  = (float*)(smc + OFF_SD);
    float* sG  = (float*)(smc + OFF_G);
    float* sA  = (float*)(smc + OFF_A);
    float* sc  = (float*)(smc + OFF_SC);
    float* ct  = sc + 32;
    float* wv  = ct + 32;
    float* spw = wv + 32;
    float* sGamT = (float*)(smc + OFF_GB);   // [(col&31)*8 + (col>>5)]
    float* sBetT = sGamT + 256;

    const int tid = threadIdx.x, wid = tid >> 5, lid = tid & 31;
    const int qm = lid >> 2, qn = (lid & 3) * 2;
    const int b  = blockIdx.x >> 1;
    const int r0 = (blockIdx.x & 1) * 128;
    const float* hb = g_h + (size_t)b * LL * HH;

    for (int i = tid; i < 65536 / 16; i += 256)
        ((uint4*)(smc + OFF_MH))[i] = make_uint4(0, 0, 0, 0);
    sGamT[(tid & 31) * 8 + (tid >> 5)] = gamma[tid];
    sBetT[(tid & 31) * 8 + (tid >> 5)] = beta_ln[tid];
    if (tid == 0) {
        spw[0] = 1.f;
        for (int i = 1; i <= CH; ++i) spw[i] = spw[i-1] * BETA;
    }
    __syncthreads();

    float acc[32][4];
    #pragma unroll
    for (int f = 0; f < 32; ++f)
        #pragma unroll
        for (int q = 0; q < 4; ++q) acc[f][q] = 0.f;

    const int klt = tid >> 3, kq = tid & 7;

    for (int t0 = 0; t0 < TT; t0 += CH) {
        const int Cc = min(CH, TT - t0);
        __syncthreads();

        // ---- (a) fused LN: pass1 stats, pass2 normalize -> fp16 KH only ----
        {
            const float4* src = (const float4*)(hb + (size_t)(t0 + klt) * HH + kq * 32);
            const bool pad = (klt >= Cc);
            float s = 0.f, sq = 0.f;
            if (!pad) {
                #pragma unroll
                for (int g = 0; g < 8; ++g) {
                    float4 v = src[g];
                    s  += v.x + v.y + v.z + v.w;
                    sq += v.x*v.x + v.y*v.y + v.z*v.z + v.w*v.w;
                }
            }
            #pragma unroll
            for (int o = 1; o < 8; o <<= 1) {
                s  += __shfl_xor_sync(0xffffffffu, s, o);
                sq += __shfl_xor_sync(0xffffffffu, sq, o);
            }
            float mu  = s * (1.0f / HH);
            float inv = rsqrtf(sq * (1.0f / HH) - mu * mu + 1e-5f);
            #pragma unroll
            for (int g = 0; g < 4; ++g) {
                float f[8];
                if (pad) {
                    #pragma unroll
                    for (int q = 0; q < 8; ++q) f[q] = 0.f;
                } else {
                    float4 v0 = src[2*g], v1 = src[2*g + 1];   // L1 hit (pass 2)
                    int cb = g * 8;   // col&31 base; bank-safe transposed gamma/beta
                    f[0] = (v0.x-mu)*inv*sGamT[(cb+0)*8+kq] + sBetT[(cb+0)*8+kq];
                    f[1] = (v0.y-mu)*inv*sGamT[(cb+1)*8+kq] + sBetT[(cb+1)*8+kq];
                    f[2] = (v0.z-mu)*inv*sGamT[(cb+2)*8+kq] + sBetT[(cb+2)*8+kq];
                    f[3] = (v0.w-mu)*inv*sGamT[(cb+3)*8+kq] + sBetT[(cb+3)*8+kq];
                    f[4] = (v1.x-mu)*inv*sGamT[(cb+4)*8+kq] + sBetT[(cb+4)*8+kq];
                    f[5] = (v1.y-mu)*inv*sGamT[(cb+5)*8+kq] + sBetT[(cb+5)*8+kq];
                    f[6] = (v1.z-mu)*inv*sGamT[(cb+6)*8+kq] + sBetT[(cb+6)*8+kq];
                    f[7] = (v1.w-mu)*inv*sGamT[(cb+7)*8+kq] + sBetT[(cb+7)*8+kq];
                }
                uint32_t off = SWZ5((uint32_t)(klt * 512 + (kq * 32 + g * 8) * 2));
                *(uint4*)(smc + OFF_KH + off) =
                    make_uint4(packh2(f[0], f[1]), packh2(f[2], f[3]),
                               packh2(f[4], f[5]), packh2(f[6], f[7]));
            }
        }
        __syncthreads();

        // ---- (b) Gram G = K K^T ----
        {
            float gacc[4] = {0.f, 0.f, 0.f, 0.f};
            const int mh = wid & 1, nq = wid >> 1;
            const uint32_t arow = (uint32_t)(16 * mh + (lid & 15)) * 512;
            const uint32_t asel = (uint32_t)((lid >> 4) << 4);
            const uint32_t brow = (uint32_t)(8 * nq + (lid & 7)) * 512;
            const uint32_t bsel = (uint32_t)(((lid >> 3) & 1) << 4);
            #pragma unroll
            for (int ks = 0; ks < 16; ++ks) {
                uint32_t ca = ks * 32;
                uint32_t ag[4], gb[2];
                ldsm_x4(ag, KH + SWZ5(arow + ca + asel));
                ldsm_x2(gb, KH + SWZ5(brow + ca + bsel));
                mma_f16(gacc, ag, gb[0], gb[1]);
            }
            int t = 16 * mh + qm, s = 8 * nq + qn;
            sG[t*36 + s] = gacc[0]; sG[t*36 + s + 1] = gacc[1];
            sG[(t+8)*36 + s] = gacc[2]; sG[(t+8)*36 + s + 1] = gacc[3];
        }
        __syncthreads();

        if (tid < 32) {
            float g = sG[tid*36 + tid];
            float s = 1.0f / (g + 1e-6f);
            sc[tid] = s;
            ct[tid] = s * spw[tid];
            wv[tid] = (tid < Cc) ? OMB * spw[Cc - 1 - tid] : 0.f;
        }
        __syncthreads();

        // ---- (c) coupling coefs + (d) U = M K^T ----
        for (int p = tid; p < 1024; p += 256) {
            int t = p >> 5, s = p & 31;
            if (s < t) sA[p] = sG[t*36 + s] * sc[t] * OMB * spw[t - 1 - s];
        }
        {
            float uacc[4][4];
            #pragma unroll
            for (int f = 0; f < 4; ++f)
                #pragma unroll
                for (int q = 0; q < 4; ++q) uacc[f][q] = 0.f;
            const uint32_t mrow = (uint32_t)(16 * wid + (lid & 15)) * 512;
            const uint32_t asel = (uint32_t)((lid >> 4) << 4);
            const uint32_t brow0 = (uint32_t)(((lid >> 4) << 3) + (lid & 7)) * 512;
            const uint32_t brow1 = brow0 + 16 * 512;
            const uint32_t bsel = (uint32_t)(((lid >> 3) & 1) << 4);
            #pragma unroll
            for (int ks = 0; ks < 16; ++ks) {
                uint32_t ca = ks * 32;
                uint32_t am[4], b0[4], b1[4];
                ldsm_x4(am, MH + SWZ5(mrow + ca + asel));
                ldsm_x4(b0, KH + SWZ5(brow0 + ca + bsel));
                ldsm_x4(b1, KH + SWZ5(brow1 + ca + bsel));
                #pragma unroll
                for (int f = 0; f < 4; ++f) {
                    const uint32_t* bh = (f < 2) ? b0 : b1;
                    int j = (f & 1) * 2;
                    mma_f16(uacc[f], am, bh[j], bh[j+1]);
                }
            }
            int i = 16 * wid + qm;
            #pragma unroll
            for (int f = 0; f < 4; ++f) {
                int lt = 8 * f + qn;
                sD[lt*128 + i]           = uacc[f][0];
                sD[(lt+1)*128 + i]       = uacc[f][1];
                sD[lt*128 + i + 8]       = uacc[f][2];
                sD[(lt+1)*128 + i + 8]   = uacc[f][3];
            }
        }
        __syncthreads();

        // ---- (e) triangular solve; rhs = fp16 K from smem (conflict-free) ----
        if (tid < 128) {
            const int i = tid;
            float d[CH];
            const uint32_t coff = (uint32_t)((r0 + i) * 2);
            #pragma unroll
            for (int t = 0; t < CH; ++t) {
                uint32_t o = SWZ5((uint32_t)(t * 512) + coff);
                float rhs = __half2float(*(const __half*)(smc + OFF_KH + o));
                d[t] = rhs - ct[t] * sD[t*128 + i];
            }
            #pragma unroll
            for (int s = 0; s < CH - 1; ++s)
                #pragma unroll
                for (int t = s + 1; t < CH; ++t)
                    d[t] -= sA[t*32 + s] * d[s];
            #pragma unroll
            for (int s = 0; s < CH; s += 2)
                *(uint32_t*)(smc + OFF_DT + i*80 + s*2) =
                    packh2(d[s] * wv[s], d[s+1] * wv[s+1]);
        }
        __syncthreads();

        // ---- (f) M update: acc = beta^Cc * acc + dT^T @ K ----
        {
            float bc = spw[Cc];
            #pragma unroll
            for (int f = 0; f < 32; ++f)
                #pragma unroll
                for (int q = 0; q < 4; ++q) acc[f][q] *= bc;
            const uint32_t adbase = (uint32_t)(16 * wid + (lid & 15)) * 80
                                  + (uint32_t)((lid >> 4) << 4);
            const uint32_t tsel = (uint32_t)((lid >> 4) << 3) * 2;
            #pragma unroll
            for (int ks = 0; ks < 2; ++ks) {
                uint32_t ad[4];
                ldsm_x4(ad, sb + OFF_DT + adbase + ks * 32);
                uint32_t trow = (uint32_t)(ks * 16 + (lid & 15)) * 512;
                #pragma unroll
                for (int jg = 0; jg < 16; ++jg) {
                    uint32_t o = SWZ5(trow + jg * 32 + tsel);
                    uint32_t bt[4];
                    ldsm_x4t(bt, KH + o);
                    mma_f16(acc[jg*2],   ad, bt[0], bt[1]);
                    mma_f16(acc[jg*2+1], ad, bt[2], bt[3]);
                }
            }
        }

        // ---- (g) publish M fp16 for next chunk ----
        if (t0 + CH < TT) {
            int r1 = 16 * wid + qm;
            #pragma unroll
            for (int f = 0; f < 32; ++f) {
                int c = f * 8 + qn;
                *(uint32_t*)(smc + OFF_MH + SWZ5((uint32_t)(r1 * 512 + c * 2))) =
                    packh2(acc[f][0], acc[f][1]);
                *(uint32_t*)(smc + OFF_MH + SWZ5((uint32_t)((r1 + 8) * 512 + c * 2))) =
                    packh2(acc[f][2], acc[f][3]);
            }
        }
    }

    // ---- final: stage fp32 M, write g_M ----
    __syncthreads();
    {
        float* SF = (float*)smc;
        int r1 = 16 * wid + qm;
        #pragma unroll
        for (int f = 0; f < 32; ++f) {
            int c = f * 8 + qn;
            SF[r1*256 + c]       = acc[f][0];
            SF[r1*256 + c + 1]   = acc[f][1];
            SF[(r1+8)*256 + c]   = acc[f][2];
            SF[(r1+8)*256 + c+1] = acc[f][3];
        }
        __syncthreads();
        const float4* sp = (const float4*)SF;
        for (int q = tid; q < 128 * 64; q += 256) {
            int i = q >> 6, j4 = q & 63;
            ((float4*)(g_M + ((size_t)b * HH + r0 + i) * HH))[j4] = sp[i*64 + j4];
        }
    }
}

// ---------------- 5. readout: y = M LN(h_last) ----------------
__global__ void k_read1(const float* __restrict__ gamma, const float* __restrict__ beta_ln) {
    int b = blockIdx.x;
    int tid = threadIdx.x;
    __shared__ float hl[HH];
    __shared__ float red[8];
    float x = g_h[((size_t)b * LL + (LL - 1)) * HH + tid];
    float s = x;
    #pragma unroll
    for (int o = 16; o; o >>= 1) s += __shfl_xor_sync(0xffffffffu, s, o);
    if ((tid & 31) == 0) red[tid >> 5] = s;
    __syncthreads();
    float mu = 0.f;
    #pragma unroll
    for (int i = 0; i < 8; ++i) mu += red[i];
    mu *= (1.0f / HH);
    __syncthreads();
    float dx = x - mu;
    float v = dx * dx;
    #pragma unroll
    for (int o = 16; o; o >>= 1) v += __shfl_xor_sync(0xffffffffu, v, o);
    if ((tid & 31) == 0) red[tid >> 5] = v;
    __syncthreads();
    float var = 0.f;
    #pragma unroll
    for (int i = 0; i < 8; ++i) var += red[i];
    var *= (1.0f / HH);
    hl[tid] = dx * rsqrtf(var + 1e-5f) * gamma[tid] + beta_ln[tid];
    __syncthreads();
    int w = tid >> 5, lane = tid & 31;
    for (int i = w; i < HH; i += 8) {
        const float* Mr = g_M + ((size_t)b * HH + i) * HH;
        float acc = 0.f;
        #pragma unroll
        for (int j = lane; j < HH; j += 32) acc += Mr[j] * hl[j];
        #pragma unroll
        for (int o = 16; o; o >>= 1) acc += __shfl_xor_sync(0xffffffffu, acc, o);
        if (lane == 0) g_y[b * HH + i] = acc;
    }
}

__global__ void k_read2(const float* __restrict__ rp_W, const float* __restrict__ rp_b) {
    int b = blockIdx.x, n = threadIdx.x;
    __shared__ float ys[HH];
    ys[n] = g_y[b * HH + n];
    __syncthreads();
    float acc = rp_b[n];
    #pragma unroll 4
    for (int k = 0; k < HH; ++k) acc += ys[k] * rp_W[k * HH + n];
    g_y2[b * HH + n] = acc;
}

static constexpr int OUT_SMEM_BYTES = (HH * 128 + BB * 257) * 4;

__global__ __launch_bounds__(256) void k_out(
    const float* __restrict__ out_W, const float* __restrict__ out_b,
    float* __restrict__ out)
{
    extern __shared__ float smf[];
    float* sW  = smf;
    float* sy2 = smf + HH * 128;
    int tid = threadIdx.x;
    int n_base = blockIdx.x * 128;

    for (int idx = tid; idx < HH * 32; idx += 256) {
        int k = idx >> 5, q = idx & 31;
        *(float4*)(sW + k*128 + q*4) = *(const float4*)(out_W + (size_t)k * VV + n_base + q*4);
    }
    for (int idx = tid; idx < BB * 64; idx += 256) {
        int bb = idx >> 6, q = idx & 63;
        float4 v = *(const float4*)(g_y2 + bb * HH + q*4);
        float* d = sy2 + bb*257 + q*4;
        d[0] = v.x; d[1] = v.y; d[2] = v.z; d[3] = v.w;
    }
    __syncthreads();

    int bg = tid >> 4, ng = tid & 15;
    int b0 = bg * 4, n0 = ng * 8;
    float acc[4][8];
    #pragma unroll
    for (int r = 0; r < 4; ++r)
        #pragma unroll
        for (int c = 0; c < 8; ++c) acc[r][c] = 0.f;
    for (int k = 0; k < HH; ++k) {
        float4 w0 = *(const float4*)(sW + k*128 + n0);
        float4 w1 = *(const float4*)(sW + k*128 + n0 + 4);
        float wv[8] = {w0.x, w0.y, w0.z, w0.w, w1.x, w1.y, w1.z, w1.w};
        #pragma unroll
        for (int r = 0; r < 4; ++r) {
            float yv = sy2[(b0+r)*257 + k];
            #pragma unroll
            for (int c = 0; c < 8; ++c) acc[r][c] += yv * wv[c];
        }
    }
    #pragma unroll
    for (int r = 0; r < 4; ++r)
        #pragma unroll
        for (int c = 0; c < 8; ++c)
            out[(size_t)(b0+r) * VV + n_base + n0 + c] = acc[r][c] + out_b[n_base + n0 + c];
}

// ---------------- launch ----------------
extern "C" void kernel_launch(void* const* d_in, const int* in_sizes, int n_in,
                              void* d_out, int out_size) {
    (void)in_sizes; (void)n_in; (void)out_size;
    const int*   seq     = (const int*)  d_in[0];
    const float* embed   = (const float*)d_in[1];
    const float* W1      = (const float*)d_in[2];
    const float* b1      = (const float*)d_in[3];
    const float* W2      = (const float*)d_in[4];
    const float* b2      = (const float*)d_in[5];
    const float* gamma   = (const float*)d_in[6];
    const float* beta_ln = (const float*)d_in[7];
    const float* rp_W    = (const float*)d_in[8];
    const float* rp_b    = (const float*)d_in[9];
    const float* out_W   = (const float*)d_in[10];
    const float* out_b   = (const float*)d_in[11];
    float* out = (float*)d_out;

    cudaFuncSetAttribute(k_ffn<1>, cudaFuncAttributeMaxDynamicSharedMemorySize, FFN_SMEM);
    cudaFuncSetAttribute(k_ffn<2>, cudaFuncAttributeMaxDynamicSharedMemorySize, FFN_SMEM);
    cudaFuncSetAttribute(k_scan,   cudaFuncAttributeMaxDynamicSharedMemorySize, SCAN_SMEM_BYTES);
    cudaFuncSetAttribute(k_out,    cudaFuncAttributeMaxDynamicSharedMemorySize, OUT_SMEM_BYTES);

    k_prep<<<512, 256>>>(W1, W2);
    k_split<<<BB * LL * 32 / 256, 256>>>(seq, embed);
    k_ffn<1><<<dim3(4, BB*LL/128), 256, FFN_SMEM>>>(seq, embed, b1);
    k_ffn<2><<<dim3(2, BB*LL/128), 256, FFN_SMEM>>>(seq, embed, b2);
    k_scan<<<BB * 2, 256, SCAN_SMEM_BYTES>>>(gamma, beta_ln);
    k_read1<<<BB, HH>>>(gamma, beta_ln);
    k_read2<<<BB, HH>>>(rp_W, rp_b);
    k_out<<<VV / 128, 256, OUT_SMEM_BYTES>>>(out_W, out_b, out);
}

// round 15
// speedup vs baseline: 1.3264x; 1.1303x over previous
#include <cuda_runtime.h>
#include <cuda_fp16.h>
#include <math.h>
#include <stdint.h>

static constexpr int BB = 64;
static constexpr int LL = 2048;
static constexpr int HH = 256;
static constexpr int VV = 32000;
static constexpr int TT = LL - 1;
static constexpr float BETA = 0.9f;
static constexpr float OMB  = 0.1f;
static constexpr int CH = 32;

// ---------------- scratch ----------------
__device__ float  g_h [(size_t)BB*LL*HH];
__device__ __half g_af[(size_t)BB*LL*HH];
__device__ __half g_ff[(size_t)BB*LL*2*HH];
__device__ __half g_w1t[512*256];
__device__ __half g_w2t[256*512];
__device__ float  g_M [(size_t)BB*HH*HH];
__device__ float  g_y [BB*HH];
__device__ float  g_y2[BB*HH];

#define SWZ(o)  ((o) ^ (((o) >> 3) & 0x70))
#define SWZ5(o) ((o) ^ (((o) >> 5) & 0x70))

__device__ __forceinline__ uint32_t smem_u32(const void* p) {
    uint32_t a;
    asm("{ .reg .u64 t; cvta.to.shared.u64 t, %1; cvt.u32.u64 %0, t; }" : "=r"(a) : "l"(p));
    return a;
}
__device__ __forceinline__ uint32_t packh2(float a, float b) {
    __half2 t = __floats2half2_rn(a, b);
    return *reinterpret_cast<uint32_t*>(&t);
}
__device__ __forceinline__ void ldsm_x4(uint32_t* r, uint32_t addr) {
    asm volatile("ldmatrix.sync.aligned.m8n8.x4.shared.b16 {%0,%1,%2,%3}, [%4];"
        : "=r"(r[0]), "=r"(r[1]), "=r"(r[2]), "=r"(r[3]) : "r"(addr));
}
__device__ __forceinline__ void ldsm_x4t(uint32_t* r, uint32_t addr) {
    asm volatile("ldmatrix.sync.aligned.m8n8.x4.trans.shared.b16 {%0,%1,%2,%3}, [%4];"
        : "=r"(r[0]), "=r"(r[1]), "=r"(r[2]), "=r"(r[3]) : "r"(addr));
}
__device__ __forceinline__ void ldsm_x2(uint32_t* r, uint32_t addr) {
    asm volatile("ldmatrix.sync.aligned.m8n8.x2.shared.b16 {%0,%1}, [%2];"
        : "=r"(r[0]), "=r"(r[1]) : "r"(addr));
}
__device__ __forceinline__ void mma_f16(float* d, const uint32_t* a, uint32_t b0, uint32_t b1) {
    asm volatile("mma.sync.aligned.m16n8k16.row.col.f32.f16.f16.f32 "
        "{%0,%1,%2,%3}, {%4,%5,%6,%7}, {%8,%9}, {%0,%1,%2,%3};"
        : "+f"(d[0]), "+f"(d[1]), "+f"(d[2]), "+f"(d[3])
        : "r"(a[0]), "r"(a[1]), "r"(a[2]), "r"(a[3]), "r"(b0), "r"(b1));
}

#define MBAR_INIT(a, cnt) \
    asm volatile("mbarrier.init.shared.b64 [%0], %1;" :: "r"((uint32_t)(a)), "r"((uint32_t)(cnt)) : "memory")
#define MBAR_TX(a, bytes) \
    asm volatile("mbarrier.arrive.expect_tx.shared.b64 _, [%0], %1;" :: "r"((uint32_t)(a)), "r"((uint32_t)(bytes)) : "memory")
#define BULK(dst, src, bytes, mbar) \
    asm volatile("cp.async.bulk.shared::cta.global.mbarrier::complete_tx::bytes [%0], [%1], %2, [%3];" \
        :: "r"((uint32_t)(dst)), "l"(src), "r"((uint32_t)(bytes)), "r"((uint32_t)(mbar)) : "memory")
#define MBAR_WAIT(a, par) do {                                                    \
    uint32_t _m = (uint32_t)(a); uint32_t _p = (uint32_t)(par); uint32_t _d;      \
    asm volatile("{\n\t.reg .pred p;\n\t"                                         \
        "mbarrier.try_wait.parity.acquire.cta.shared::cta.b64 p, [%1], %2;\n\t"   \
        "selp.b32 %0, 1, 0, p;\n\t}"                                              \
        : "=r"(_d) : "r"(_m), "r"(_p) : "memory");                                \
    if (!_d) {                                                                    \
        asm volatile("{\n\t.reg .pred P1;\n\t"                                    \
            "WL_%=:\n\t"                                                          \
            "mbarrier.try_wait.parity.acquire.cta.shared::cta.b64 P1, [%0], %1, 0x989680;\n\t" \
            "@P1 bra.uni WD_%=;\n\t"                                              \
            "bra.uni WL_%=;\n\t"                                                  \
            "WD_%=:\n\t}"                                                         \
            :: "r"(_m), "r"(_p) : "memory");                                      \
    }                                                                             \
} while (0)

// ---------------- 0a. weights -> fp16, tiled-swizzled 16KB tiles ----------------
__global__ void k_prep(const float* __restrict__ W1, const float* __restrict__ W2) {
    int idx = blockIdx.x * blockDim.x + threadIdx.x;
    {
        int n = idx >> 8, k = idx & 255;
        __half v = __float2half_rn(W1[k * 512 + n]);
        size_t off = (((size_t)(n >> 7) * 4 + (k >> 6)) << 14)
                   + SWZ((uint32_t)((n & 127) * 128 + (k & 63) * 2));
        *(__half*)((char*)g_w1t + off) = v;
    }
    {
        int n = idx >> 9, k = idx & 511;
        __half v = __float2half_rn(W2[k * 256 + n]);
        size_t off = (((size_t)(n >> 7) * 8 + (k >> 6)) << 14)
                   + SWZ((uint32_t)((n & 127) * 128 + (k & 63) * 2));
        *(__half*)((char*)g_w2t + off) = v;
    }
}

// ---------------- 0b. gather -> fp16 tiled-swizzled ----------------
__global__ void k_split(const int* __restrict__ seq, const float* __restrict__ embed) {
    size_t idx = (size_t)blockIdx.x * blockDim.x + threadIdx.x;
    int row = (int)(idx >> 5), g = (int)(idx & 31);
    int tok = seq[row];
    const float4* src = (const float4*)(embed + (size_t)tok * HH + g * 8);
    float4 v0 = src[0], v1 = src[1];
    uint4 o = make_uint4(packh2(v0.x, v0.y), packh2(v0.z, v0.w),
                         packh2(v1.x, v1.y), packh2(v1.z, v1.w));
    int mt = row >> 7, c = g >> 3;
    size_t off = (((size_t)mt * 4 + c) << 14)
               + SWZ((uint32_t)((row & 127) * 128 + (g & 7) * 16));
    *(uint4*)((char*)g_af + off) = o;
}

// ---------------- 1+2. FFN: fp16 HMMA + cp.async.bulk 2-stage ----------------
static constexpr int FFN_SMEM = 1024 + 65536 + 64;

__device__ __forceinline__ void ffn_compute(uint32_t aB, uint32_t bB,
                                            int wm, int wn, int lid, float (&acc)[4][4][4])
{
    #pragma unroll
    for (int ks = 0; ks < 4; ++ks) {
        uint32_t colA = ks * 32 + ((lid >> 4) << 4);
        uint32_t ah[4][4];
        #pragma unroll
        for (int mf = 0; mf < 4; ++mf) {
            uint32_t row = wm * 64 + mf * 16 + (lid & 15);
            ldsm_x4(ah[mf], aB + SWZ(row * 128 + colA));
        }
        uint32_t bh[2][4];
        #pragma unroll
        for (int nf = 0; nf < 2; ++nf) {
            uint32_t row = wn * 32 + nf * 16 + ((lid >> 4) << 3) + (lid & 7);
            uint32_t colB = ks * 32 + (((lid >> 3) & 1) << 4);
            ldsm_x4(bh[nf], bB + SWZ(row * 128 + colB));
        }
        #pragma unroll
        for (int mf = 0; mf < 4; ++mf)
            #pragma unroll
            for (int nf = 0; nf < 2; ++nf)
                #pragma unroll
                for (int j = 0; j < 2; ++j)
                    mma_f16(acc[mf][nf*2+j], ah[mf], bh[nf][j*2], bh[nf][j*2+1]);
    }
}

template<int PHASE>
__global__ __launch_bounds__(256, 2) void k_ffn(
    const int* __restrict__ seq, const float* __restrict__ embed,
    const float* __restrict__ bias)
{
    constexpr int NC = (PHASE == 1) ? 4 : 8;

    extern __shared__ char sm[];
    int*   sseq  = (int*)sm;
    float* sbias = (float*)(sm + 512);
    const uint32_t sb = smem_u32(sm);
    const uint32_t st0 = sb + 1024, st1 = sb + 1024 + 32768;
    const uint32_t mb  = sb + 1024 + 65536;

    const int tid = threadIdx.x, wid = tid >> 5, lid = tid & 31;
    const int wm = wid & 1, wn = wid >> 1;
    const int mt = blockIdx.y, nb0 = blockIdx.x * 128;

    const char* Atl = (const char*)((PHASE == 1) ? (const void*)g_af : (const void*)g_ff)
                    + (((size_t)mt * NC) << 14);
    const char* Btl = (const char*)((PHASE == 1) ? (const void*)g_w1t : (const void*)g_w2t)
                    + (((size_t)blockIdx.x * NC) << 14);

    if (tid < 128) {
        sbias[tid] = bias[nb0 + tid];
        if (PHASE == 2) sseq[tid] = seq[mt * 128 + tid];
    }
    if (tid == 0) { MBAR_INIT(mb, 1); MBAR_INIT(mb + 8, 1); }
    __syncthreads();

    if (tid == 0) {
        MBAR_TX(mb, 32768);
        BULK(st0, Atl, 16384, mb);
        BULK(st0 + 16384, Btl, 16384, mb);
        MBAR_TX(mb + 8, 32768);
        BULK(st1, Atl + 16384, 16384, mb + 8);
        BULK(st1 + 16384, Btl + 16384, 16384, mb + 8);
    }

    float acc[4][4][4];
    #pragma unroll
    for (int a = 0; a < 4; ++a)
        #pragma unroll
        for (int b = 0; b < 4; ++b)
            #pragma unroll
            for (int c = 0; c < 4; ++c) acc[a][b][c] = 0.f;

    for (int c = 0; c < NC; ++c) {
        int s = c & 1;
        uint32_t stg = s ? st1 : st0;
        MBAR_WAIT(mb + s * 8, (c >> 1) & 1);
        ffn_compute(stg, stg + 16384, wm, wn, lid, acc);
        __syncthreads();
        if (tid == 0 && c + 2 < NC) {
            MBAR_TX(mb + s * 8, 32768);
            BULK(stg, Atl + ((size_t)(c + 2) << 14), 16384, mb + s * 8);
            BULK(stg + 16384, Btl + ((size_t)(c + 2) << 14), 16384, mb + s * 8);
        }
    }

    const int qm = lid >> 2, qn = (lid & 3) * 2;
    if (PHASE == 1) {
        uint32_t* SH = (uint32_t*)(sm + 1024);
        #pragma unroll
        for (int mf = 0; mf < 4; ++mf)
            #pragma unroll
            for (int nf = 0; nf < 2; ++nf)
                #pragma unroll
                for (int j = 0; j < 2; ++j) {
                    const float* d = acc[mf][nf*2+j];
                    int nl = wn * 32 + nf * 16 + j * 8 + qn;
                    #pragma unroll
                    for (int hh = 0; hh < 2; ++hh) {
                        int ml = wm * 64 + mf * 16 + qm + hh * 8;
                        float v0 = fmaxf(d[hh*2+0] + sbias[nl],   0.f);
                        float v1 = fmaxf(d[hh*2+1] + sbias[nl+1], 0.f);
                        SH[ml * 64 + (nl >> 1)] = packh2(v0, v1);
                    }
                }
        __syncthreads();
        char* gff = (char*)g_ff;
        #pragma unroll
        for (int t = 0; t < 8; ++t) {
            int idx = t * 256 + tid;
            int tile = idx >> 10, rem = idx & 1023;
            int r = rem >> 3, j = rem & 7;
            uint4 v = ((const uint4*)SH)[r * 16 + tile * 8 + j];
            size_t off = (((size_t)mt * 8 + blockIdx.x * 2 + tile) << 14)
                       + SWZ((uint32_t)(r * 128 + j * 16));
            *(uint4*)(gff + off) = v;
        }
    } else {
        float* SF = (float*)(sm + 1024);
        #pragma unroll
        for (int mf = 0; mf < 4; ++mf)
            #pragma unroll
            for (int nf = 0; nf < 2; ++nf)
                #pragma unroll
                for (int j = 0; j < 2; ++j) {
                    const float* d = acc[mf][nf*2+j];
                    int nl = wn * 32 + nf * 16 + j * 8 + qn;
                    #pragma unroll
                    for (int hh = 0; hh < 2; ++hh) {
                        int ml = wm * 64 + mf * 16 + qm + hh * 8;
                        SF[ml * 128 + nl]     = d[hh*2+0] + sbias[nl];
                        SF[ml * 128 + nl + 1] = d[hh*2+1] + sbias[nl+1];
                    }
                }
        __syncthreads();
        int row = tid >> 1, part = tid & 1;
        int tok = sseq[row];
        const float4* ep = (const float4*)(embed + (size_t)tok * HH + nb0);
        const float4* sfp = (const float4*)(SF + row * 128);
        float4* gp = (float4*)(g_h + ((size_t)mt * 128 + row) * HH + nb0);
        #pragma unroll
        for (int j = 0; j < 16; ++j) {
            int c4 = part * 16 + j;
            float4 f = sfp[c4];
            float4 e = ep[c4];
            f.x += e.x; f.y += e.y; f.z += e.z; f.w += e.w;
            gp[c4] = f;
        }
    }
}

// ---------------- 3. LayerNorm: one warp per row, float4 (in place) ----------------
__global__ void k_ln(const float* __restrict__ gamma, const float* __restrict__ beta_ln) {
    int warp = threadIdx.x >> 5, lane = threadIdx.x & 31;
    size_t row = (size_t)blockIdx.x * 8 + warp;
    float4* xp = (float4*)(g_h + row * HH);
    float4 a = xp[lane * 2];
    float4 b = xp[lane * 2 + 1];
    float s = a.x + a.y + a.z + a.w + b.x + b.y + b.z + b.w;
    #pragma unroll
    for (int o = 16; o; o >>= 1) s += __shfl_xor_sync(0xffffffffu, s, o);
    float mu = s * (1.0f / HH);
    float dx[8] = {a.x-mu, a.y-mu, a.z-mu, a.w-mu, b.x-mu, b.y-mu, b.z-mu, b.w-mu};
    float v = 0.f;
    #pragma unroll
    for (int q = 0; q < 8; ++q) v += dx[q] * dx[q];
    #pragma unroll
    for (int o = 16; o; o >>= 1) v += __shfl_xor_sync(0xffffffffu, v, o);
    float inv = rsqrtf(v * (1.0f / HH) + 1e-5f);
    float4 g0 = ((const float4*)gamma)[lane * 2];
    float4 g1 = ((const float4*)gamma)[lane * 2 + 1];
    float4 t0 = ((const float4*)beta_ln)[lane * 2];
    float4 t1 = ((const float4*)beta_ln)[lane * 2 + 1];
    float4 o0, o1;
    o0.x = dx[0]*inv*g0.x + t0.x; o0.y = dx[1]*inv*g0.y + t0.y;
    o0.z = dx[2]*inv*g0.z + t0.z; o0.w = dx[3]*inv*g0.w + t0.w;
    o1.x = dx[4]*inv*g1.x + t1.x; o1.y = dx[5]*inv*g1.y + t1.y;
    o1.z = dx[6]*inv*g1.z + t1.z; o1.w = dx[7]*inv*g1.w + t1.w;
    xp[lane * 2]     = o0;
    xp[lane * 2 + 1] = o1;
}

// ---------------- 4. scan: single-term fp16 HMMA chunked delta rule (round-10) ----------------
static constexpr uint32_t OFF_MH  = 0;        // [128][512B] fp16 swz5
static constexpr uint32_t OFF_KH  = 65536;    // [32][512B] fp16 swz5
static constexpr uint32_t OFF_SD  = 81920;    // [32][128] f32 raw U
static constexpr uint32_t OFF_DT  = 98304;    // [128][80B] fp16 weighted d^T
static constexpr uint32_t OFF_G   = 108544;   // [32][36] f32
static constexpr uint32_t OFF_A   = 113152;   // [32][32] f32
static constexpr uint32_t OFF_SC  = 117248;   // sc, ct, wv, spw (1024B reserved)
static constexpr int SCAN_SMEM_BYTES = 131584; // >= 131072 final staging

__global__ __launch_bounds__(256, 1) void k_scan() {
    extern __shared__ char smc[];
    const uint32_t sb = smem_u32(smc);
    const uint32_t MH = sb + OFF_MH;
    const uint32_t KH = sb + OFF_KH;
    float* sD  = (float*)(smc + OFF_SD);
    float* sG  = (float*)(smc + OFF_G);
    float* sA  = (float*)(smc + OFF_A);
    float* sc  = (float*)(smc + OFF_SC);
    float* ct  = sc + 32;
    float* wv  = ct + 32;
    float* spw = wv + 32;

    const int tid = threadIdx.x, wid = tid >> 5, lid = tid & 31;
    const int qm = lid >> 2, qn = (lid & 3) * 2;
    const int b  = blockIdx.x >> 1;
    const int r0 = (blockIdx.x & 1) * 128;
    const float* hb = g_h + (size_t)b * LL * HH;

    for (int i = tid; i < 65536 / 16; i += 256)
        ((uint4*)(smc + OFF_MH))[i] = make_uint4(0, 0, 0, 0);
    if (tid == 0) {
        spw[0] = 1.f;
        for (int i = 1; i <= CH; ++i) spw[i] = spw[i-1] * BETA;
    }
    __syncthreads();

    float acc[32][4];
    #pragma unroll
    for (int f = 0; f < 32; ++f)
        #pragma unroll
        for (int q = 0; q < 4; ++q) acc[f][q] = 0.f;

    const int klt = tid >> 3, kq = tid & 7;

    for (int t0 = 0; t0 < TT; t0 += CH) {
        const int Cc = min(CH, TT - t0);
        __syncthreads();

        // ---- (a) K chunk -> fp16 swz5 ----
        {
            const float* src = hb + (size_t)(t0 + klt) * HH + kq * 32;
            bool pad = (klt >= Cc);
            #pragma unroll
            for (int g = 0; g < 4; ++g) {
                float f[8];
                if (pad) {
                    #pragma unroll
                    for (int q = 0; q < 8; ++q) f[q] = 0.f;
                } else {
                    float4 v0 = *(const float4*)(src + g*8);
                    float4 v1 = *(const float4*)(src + g*8 + 4);
                    f[0]=v0.x; f[1]=v0.y; f[2]=v0.z; f[3]=v0.w;
                    f[4]=v1.x; f[5]=v1.y; f[6]=v1.z; f[7]=v1.w;
                }
                uint32_t off = SWZ5((uint32_t)(klt * 512 + (kq * 32 + g * 8) * 2));
                *(uint4*)(smc + OFF_KH + off) =
                    make_uint4(packh2(f[0], f[1]), packh2(f[2], f[3]),
                               packh2(f[4], f[5]), packh2(f[6], f[7]));
            }
        }
        __syncthreads();

        // ---- (b) Gram G = K K^T ----
        {
            float gacc[4] = {0.f, 0.f, 0.f, 0.f};
            const int mh = wid & 1, nq = wid >> 1;
            const uint32_t arow = (uint32_t)(16 * mh + (lid & 15)) * 512;
            const uint32_t asel = (uint32_t)((lid >> 4) << 4);
            const uint32_t brow = (uint32_t)(8 * nq + (lid & 7)) * 512;
            const uint32_t bsel = (uint32_t)(((lid >> 3) & 1) << 4);
            #pragma unroll
            for (int ks = 0; ks < 16; ++ks) {
                uint32_t ca = ks * 32;
                uint32_t ag[4], gb[2];
                ldsm_x4(ag, KH + SWZ5(arow + ca + asel));
                ldsm_x2(gb, KH + SWZ5(brow + ca + bsel));
                mma_f16(gacc, ag, gb[0], gb[1]);
            }
            int t = 16 * mh + qm, s = 8 * nq + qn;
            sG[t*36 + s] = gacc[0]; sG[t*36 + s + 1] = gacc[1];
            sG[(t+8)*36 + s] = gacc[2]; sG[(t+8)*36 + s + 1] = gacc[3];
        }
        __syncthreads();

        if (tid < 32) {
            float g = sG[tid*36 + tid];
            float s = 1.0f / (g + 1e-6f);
            sc[tid] = s;
            ct[tid] = s * spw[tid];
            wv[tid] = (tid < Cc) ? OMB * spw[Cc - 1 - tid] : 0.f;
        }
        __syncthreads();

        // ---- (c) coupling coefs + (d) U = M K^T ----
        for (int p = tid; p < 1024; p += 256) {
            int t = p >> 5, s = p & 31;
            if (s < t) sA[p] = sG[t*36 + s] * sc[t] * OMB * spw[t - 1 - s];
        }
        {
            float uacc[4][4];
            #pragma unroll
            for (int f = 0; f < 4; ++f)
                #pragma unroll
                for (int q = 0; q < 4; ++q) uacc[f][q] = 0.f;
            const uint32_t mrow = (uint32_t)(16 * wid + (lid & 15)) * 512;
            const uint32_t asel = (uint32_t)((lid >> 4) << 4);
            const uint32_t brow0 = (uint32_t)(((lid >> 4) << 3) + (lid & 7)) * 512;
            const uint32_t brow1 = brow0 + 16 * 512;
            const uint32_t bsel = (uint32_t)(((lid >> 3) & 1) << 4);
            #pragma unroll
            for (int ks = 0; ks < 16; ++ks) {
                uint32_t ca = ks * 32;
                uint32_t am[4], b0[4], b1[4];
                ldsm_x4(am, MH + SWZ5(mrow + ca + asel));
                ldsm_x4(b0, KH + SWZ5(brow0 + ca + bsel));
                ldsm_x4(b1, KH + SWZ5(brow1 + ca + bsel));
                #pragma unroll
                for (int f = 0; f < 4; ++f) {
                    const uint32_t* bh = (f < 2) ? b0 : b1;
                    int j = (f & 1) * 2;
                    mma_f16(uacc[f], am, bh[j], bh[j+1]);
                }
            }
            int i = 16 * wid + qm;
            #pragma unroll
            for (int f = 0; f < 4; ++f) {
                int lt = 8 * f + qn;
                sD[lt*128 + i]           = uacc[f][0];
                sD[(lt+1)*128 + i]       = uacc[f][1];
                sD[lt*128 + i + 8]       = uacc[f][2];
                sD[(lt+1)*128 + i + 8]   = uacc[f][3];
            }
        }
        __syncthreads();

        // ---- (e) triangular solve; rhs = fp32 h from global (L1/L2 hot) ----
        if (tid < 128) {
            const int i = tid;
            float d[CH];
            #pragma unroll
            for (int t = 0; t < CH; ++t) {
                float rhs = (t < Cc) ? hb[(size_t)(t0 + t) * HH + r0 + i] : 0.f;
                d[t] = rhs - ct[t] * sD[t*128 + i];
            }
            #pragma unroll
            for (int s = 0; s < CH - 1; ++s)
                #pragma unroll
                for (int t = s + 1; t < CH; ++t)
                    d[t] -= sA[t*32 + s] * d[s];
            #pragma unroll
            for (int s = 0; s < CH; s += 2)
                *(uint32_t*)(smc + OFF_DT + i*80 + s*2) =
                    packh2(d[s] * wv[s], d[s+1] * wv[s+1]);
        }
        __syncthreads();

        // ---- (f) M update: acc = beta^Cc * acc + dT^T @ K ----
        {
            float bc = spw[Cc];
            #pragma unroll
            for (int f = 0; f < 32; ++f)
                #pragma unroll
                for (int q = 0; q < 4; ++q) acc[f][q] *= bc;
            const uint32_t adbase = (uint32_t)(16 * wid + (lid & 15)) * 80
                                  + (uint32_t)((lid >> 4) << 4);
            const uint32_t tsel = (uint32_t)((lid >> 4) << 3) * 2;
            #pragma unroll
            for (int ks = 0; ks < 2; ++ks) {
                uint32_t ad[4];
                ldsm_x4(ad, sb + OFF_DT + adbase + ks * 32);
                uint32_t trow = (uint32_t)(ks * 16 + (lid & 15)) * 512;
                #pragma unroll
                for (int jg = 0; jg < 16; ++jg) {
                    uint32_t o = SWZ5(trow + jg * 32 + tsel);
                    uint32_t bt[4];
                    ldsm_x4t(bt, KH + o);
                    mma_f16(acc[jg*2],   ad, bt[0], bt[1]);
                    mma_f16(acc[jg*2+1], ad, bt[2], bt[3]);
                }
            }
        }

        // ---- (g) publish M fp16 for next chunk ----
        if (t0 + CH < TT) {
            int r1 = 16 * wid + qm;
            #pragma unroll
            for (int f = 0; f < 32; ++f) {
                int c = f * 8 + qn;
                *(uint32_t*)(smc + OFF_MH + SWZ5((uint32_t)(r1 * 512 + c * 2))) =
                    packh2(acc[f][0], acc[f][1]);
                *(uint32_t*)(smc + OFF_MH + SWZ5((uint32_t)((r1 + 8) * 512 + c * 2))) =
                    packh2(acc[f][2], acc[f][3]);
            }
        }
    }

    // ---- final: stage fp32 M, write g_M ----
    __syncthreads();
    {
        float* SF = (float*)smc;
        int r1 = 16 * wid + qm;
        #pragma unroll
        for (int f = 0; f < 32; ++f) {
            int c = f * 8 + qn;
            SF[r1*256 + c]       = acc[f][0];
            SF[r1*256 + c + 1]   = acc[f][1];
            SF[(r1+8)*256 + c]   = acc[f][2];
            SF[(r1+8)*256 + c+1] = acc[f][3];
        }
        __syncthreads();
        const float4* sp = (const float4*)SF;
        for (int q = tid; q < 128 * 64; q += 256) {
            int i = q >> 6, j4 = q & 63;
            ((float4*)(g_M + ((size_t)b * HH + r0 + i) * HH))[j4] = sp[i*64 + j4];
        }
    }
}

// ---------------- 5-7. readout ----------------
__global__ void k_read1() {
    int b = blockIdx.x;
    int tid = threadIdx.x;
    __shared__ float hl[HH];
    hl[tid] = g_h[((size_t)b * LL + (LL - 1)) * HH + tid];
    __syncthreads();
    int w = tid >> 5, lane = tid & 31;
    for (int i = w; i < HH; i += 8) {
        const float* Mr = g_M + ((size_t)b * HH + i) * HH;
        float s = 0.f;
        #pragma unroll
        for (int j = lane; j < HH; j += 32) s += Mr[j] * hl[j];
        #pragma unroll
        for (int o = 16; o; o >>= 1) s += __shfl_xor_sync(0xffffffffu, s, o);
        if (lane == 0) g_y[b * HH + i] = s;
    }
}
__global__ void k_read2(const float* __restrict__ rp_W, const float* __restrict__ rp_b) {
    int b = blockIdx.x, n = threadIdx.x;
    __shared__ float ys[HH];
    ys[n] = g_y[b * HH + n];
    __syncthreads();
    float acc = rp_b[n];
    #pragma unroll 4
    for (int k = 0; k < HH; ++k) acc += ys[k] * rp_W[k * HH + n];
    g_y2[b * HH + n] = acc;
}

static constexpr int OUT_SMEM_BYTES = (HH * 128 + BB * 257) * 4;

__global__ __launch_bounds__(256) void k_out(
    const float* __restrict__ out_W, const float* __restrict__ out_b,
    float* __restrict__ out)
{
    extern __shared__ float smf[];
    float* sW  = smf;
    float* sy2 = smf + HH * 128;
    int tid = threadIdx.x;
    int n_base = blockIdx.x * 128;

    for (int idx = tid; idx < HH * 32; idx += 256) {
        int k = idx >> 5, q = idx & 31;
        *(float4*)(sW + k*128 + q*4) = *(const float4*)(out_W + (size_t)k * VV + n_base + q*4);
    }
    for (int idx = tid; idx < BB * 64; idx += 256) {
        int bb = idx >> 6, q = idx & 63;
        float4 v = *(const float4*)(g_y2 + bb * HH + q*4);
        float* d = sy2 + bb*257 + q*4;
        d[0] = v.x; d[1] = v.y; d[2] = v.z; d[3] = v.w;
    }
    __syncthreads();

    int bg = tid >> 4, ng = tid & 15;
    int b0 = bg * 4, n0 = ng * 8;
    float acc[4][8];
    #pragma unroll
    for (int r = 0; r < 4; ++r)
        #pragma unroll
        for (int c = 0; c < 8; ++c) acc[r][c] = 0.f;
    for (int k = 0; k < HH; ++k) {
        float4 w0 = *(const float4*)(sW + k*128 + n0);
        float4 w1 = *(const float4*)(sW + k*128 + n0 + 4);
        float wv[8] = {w0.x, w0.y, w0.z, w0.w, w1.x, w1.y, w1.z, w1.w};
        #pragma unroll
        for (int r = 0; r < 4; ++r) {
            float yv = sy2[(b0+r)*257 + k];
            #pragma unroll
            for (int c = 0; c < 8; ++c) acc[r][c] += yv * wv[c];
        }
    }
    #pragma unroll
    for (int r = 0; r < 4; ++r)
        #pragma unroll
        for (int c = 0; c < 8; ++c)
            out[(size_t)(b0+r) * VV + n_base + n0 + c] = acc[r][c] + out_b[n_base + n0 + c];
}

// ---------------- launch ----------------
extern "C" void kernel_launch(void* const* d_in, const int* in_sizes, int n_in,
                              void* d_out, int out_size) {
    (void)in_sizes; (void)n_in; (void)out_size;
    const int*   seq     = (const int*)  d_in[0];
    const float* embed   = (const float*)d_in[1];
    const float* W1      = (const float*)d_in[2];
    const float* b1      = (const float*)d_in[3];
    const float* W2      = (const float*)d_in[4];
    const float* b2      = (const float*)d_in[5];
    const float* gamma   = (const float*)d_in[6];
    const float* beta_ln = (const float*)d_in[7];
    const float* rp_W    = (const float*)d_in[8];
    const float* rp_b    = (const float*)d_in[9];
    const float* out_W   = (const float*)d_in[10];
    const float* out_b   = (const float*)d_in[11];
    float* out = (float*)d_out;

    cudaFuncSetAttribute(k_ffn<1>, cudaFuncAttributeMaxDynamicSharedMemorySize, FFN_SMEM);
    cudaFuncSetAttribute(k_ffn<2>, cudaFuncAttributeMaxDynamicSharedMemorySize, FFN_SMEM);
    cudaFuncSetAttribute(k_scan,   cudaFuncAttributeMaxDynamicSharedMemorySize, SCAN_SMEM_BYTES);
    cudaFuncSetAttribute(k_out,    cudaFuncAttributeMaxDynamicSharedMemorySize, OUT_SMEM_BYTES);

    k_prep<<<512, 256>>>(W1, W2);
    k_split<<<BB * LL * 32 / 256, 256>>>(seq, embed);
    k_ffn<1><<<dim3(4, BB*LL/128), 256, FFN_SMEM>>>(seq, embed, b1);
    k_ffn<2><<<dim3(2, BB*LL/128), 256, FFN_SMEM>>>(seq, embed, b2);
    k_ln<<<BB * LL / 8, 256>>>(gamma, beta_ln);
    k_scan<<<BB * 2, 256, SCAN_SMEM_BYTES>>>();
    k_read1<<<BB, 256>>>();
    k_read2<<<BB, HH>>>(rp_W, rp_b);
    k_out<<<VV / 128, 256, OUT_SMEM_BYTES>>>(out_W, out_b, out);
}

// round 16
// speedup vs baseline: 1.5132x; 1.1408x over previous
#include <cuda_runtime.h>
#include <cuda_fp16.h>
#include <math.h>
#include <stdint.h>

static constexpr int BB = 64;
static constexpr int LL = 2048;
static constexpr int HH = 256;
static constexpr int VV = 32000;
static constexpr int TT = LL - 1;
static constexpr float BETA = 0.9f;
static constexpr float OMB  = 0.1f;
static constexpr int CH = 32;
static constexpr int NCH = 64;   // chunks per batch

// ---------------- scratch ----------------
__device__ float  g_h [(size_t)BB*LL*HH];
__device__ __half g_hh[(size_t)BB*LL*HH];       // normalized h, fp16 swz5 16KB tiles
__device__ __half g_af[(size_t)BB*LL*HH];
__device__ __half g_ff[(size_t)BB*LL*2*HH];
__device__ __half g_w1t[512*256];
__device__ __half g_w2t[256*512];
__device__ float  g_M [(size_t)BB*HH*HH];
__device__ float  g_y [BB*HH];
__device__ float  g_y2[BB*HH];

#define SWZ(o)  ((o) ^ (((o) >> 3) & 0x70))
#define SWZ5(o) ((o) ^ (((o) >> 5) & 0x70))

__device__ __forceinline__ uint32_t smem_u32(const void* p) {
    uint32_t a;
    asm("{ .reg .u64 t; cvta.to.shared.u64 t, %1; cvt.u32.u64 %0, t; }" : "=r"(a) : "l"(p));
    return a;
}
__device__ __forceinline__ uint32_t packh2(float a, float b) {
    __half2 t = __floats2half2_rn(a, b);
    return *reinterpret_cast<uint32_t*>(&t);
}
__device__ __forceinline__ void ldsm_x4(uint32_t* r, uint32_t addr) {
    asm volatile("ldmatrix.sync.aligned.m8n8.x4.shared.b16 {%0,%1,%2,%3}, [%4];"
        : "=r"(r[0]), "=r"(r[1]), "=r"(r[2]), "=r"(r[3]) : "r"(addr));
}
__device__ __forceinline__ void ldsm_x4t(uint32_t* r, uint32_t addr) {
    asm volatile("ldmatrix.sync.aligned.m8n8.x4.trans.shared.b16 {%0,%1,%2,%3}, [%4];"
        : "=r"(r[0]), "=r"(r[1]), "=r"(r[2]), "=r"(r[3]) : "r"(addr));
}
__device__ __forceinline__ void ldsm_x2(uint32_t* r, uint32_t addr) {
    asm volatile("ldmatrix.sync.aligned.m8n8.x2.shared.b16 {%0,%1}, [%2];"
        : "=r"(r[0]), "=r"(r[1]) : "r"(addr));
}
__device__ __forceinline__ void mma_f16(float* d, const uint32_t* a, uint32_t b0, uint32_t b1) {
    asm volatile("mma.sync.aligned.m16n8k16.row.col.f32.f16.f16.f32 "
        "{%0,%1,%2,%3}, {%4,%5,%6,%7}, {%8,%9}, {%0,%1,%2,%3};"
        : "+f"(d[0]), "+f"(d[1]), "+f"(d[2]), "+f"(d[3])
        : "r"(a[0]), "r"(a[1]), "r"(a[2]), "r"(a[3]), "r"(b0), "r"(b1));
}

#define MBAR_INIT(a, cnt) \
    asm volatile("mbarrier.init.shared.b64 [%0], %1;" :: "r"((uint32_t)(a)), "r"((uint32_t)(cnt)) : "memory")
#define MBAR_TX(a, bytes) \
    asm volatile("mbarrier.arrive.expect_tx.shared.b64 _, [%0], %1;" :: "r"((uint32_t)(a)), "r"((uint32_t)(bytes)) : "memory")
#define BULK(dst, src, bytes, mbar) \
    asm volatile("cp.async.bulk.shared::cta.global.mbarrier::complete_tx::bytes [%0], [%1], %2, [%3];" \
        :: "r"((uint32_t)(dst)), "l"(src), "r"((uint32_t)(bytes)), "r"((uint32_t)(mbar)) : "memory")
#define MBAR_WAIT(a, par) do {                                                    \
    uint32_t _m = (uint32_t)(a); uint32_t _p = (uint32_t)(par); uint32_t _d;      \
    asm volatile("{\n\t.reg .pred p;\n\t"                                         \
        "mbarrier.try_wait.parity.acquire.cta.shared::cta.b64 p, [%1], %2;\n\t"   \
        "selp.b32 %0, 1, 0, p;\n\t}"                                              \
        : "=r"(_d) : "r"(_m), "r"(_p) : "memory");                                \
    if (!_d) {                                                                    \
        asm volatile("{\n\t.reg .pred P1;\n\t"                                    \
            "WL_%=:\n\t"                                                          \
            "mbarrier.try_wait.parity.acquire.cta.shared::cta.b64 P1, [%0], %1, 0x989680;\n\t" \
            "@P1 bra.uni WD_%=;\n\t"                                              \
            "bra.uni WL_%=;\n\t"                                                  \
            "WD_%=:\n\t}"                                                         \
            :: "r"(_m), "r"(_p) : "memory");                                      \
    }                                                                             \
} while (0)

// ---------------- 0a. weights -> fp16, tiled-swizzled 16KB tiles ----------------
__global__ void k_prep(const float* __restrict__ W1, const float* __restrict__ W2) {
    int idx = blockIdx.x * blockDim.x + threadIdx.x;
    {
        int n = idx >> 8, k = idx & 255;
        __half v = __float2half_rn(W1[k * 512 + n]);
        size_t off = (((size_t)(n >> 7) * 4 + (k >> 6)) << 14)
                   + SWZ((uint32_t)((n & 127) * 128 + (k & 63) * 2));
        *(__half*)((char*)g_w1t + off) = v;
    }
    {
        int n = idx >> 9, k = idx & 511;
        __half v = __float2half_rn(W2[k * 256 + n]);
        size_t off = (((size_t)(n >> 7) * 8 + (k >> 6)) << 14)
                   + SWZ((uint32_t)((n & 127) * 128 + (k & 63) * 2));
        *(__half*)((char*)g_w2t + off) = v;
    }
}

// ---------------- 0b. gather -> fp16 tiled-swizzled ----------------
__global__ void k_split(const int* __restrict__ seq, const float* __restrict__ embed) {
    size_t idx = (size_t)blockIdx.x * blockDim.x + threadIdx.x;
    int row = (int)(idx >> 5), g = (int)(idx & 31);
    int tok = seq[row];
    const float4* src = (const float4*)(embed + (size_t)tok * HH + g * 8);
    float4 v0 = src[0], v1 = src[1];
    uint4 o = make_uint4(packh2(v0.x, v0.y), packh2(v0.z, v0.w),
                         packh2(v1.x, v1.y), packh2(v1.z, v1.w));
    int mt = row >> 7, c = g >> 3;
    size_t off = (((size_t)mt * 4 + c) << 14)
               + SWZ((uint32_t)((row & 127) * 128 + (g & 7) * 16));
    *(uint4*)((char*)g_af + off) = o;
}

// ---------------- 1+2. FFN: fp16 HMMA + cp.async.bulk 2-stage ----------------
static constexpr int FFN_SMEM = 1024 + 65536 + 64;

__device__ __forceinline__ void ffn_compute(uint32_t aB, uint32_t bB,
                                            int wm, int wn, int lid, float (&acc)[4][4][4])
{
    #pragma unroll
    for (int ks = 0; ks < 4; ++ks) {
        uint32_t colA = ks * 32 + ((lid >> 4) << 4);
        uint32_t ah[4][4];
        #pragma unroll
        for (int mf = 0; mf < 4; ++mf) {
            uint32_t row = wm * 64 + mf * 16 + (lid & 15);
            ldsm_x4(ah[mf], aB + SWZ(row * 128 + colA));
        }
        uint32_t bh[2][4];
        #pragma unroll
        for (int nf = 0; nf < 2; ++nf) {
            uint32_t row = wn * 32 + nf * 16 + ((lid >> 4) << 3) + (lid & 7);
            uint32_t colB = ks * 32 + (((lid >> 3) & 1) << 4);
            ldsm_x4(bh[nf], bB + SWZ(row * 128 + colB));
        }
        #pragma unroll
        for (int mf = 0; mf < 4; ++mf)
            #pragma unroll
            for (int nf = 0; nf < 2; ++nf)
                #pragma unroll
                for (int j = 0; j < 2; ++j)
                    mma_f16(acc[mf][nf*2+j], ah[mf], bh[nf][j*2], bh[nf][j*2+1]);
    }
}

template<int PHASE>
__global__ __launch_bounds__(256, 2) void k_ffn(
    const int* __restrict__ seq, const float* __restrict__ embed,
    const float* __restrict__ bias)
{
    constexpr int NC = (PHASE == 1) ? 4 : 8;

    extern __shared__ char sm[];
    int*   sseq  = (int*)sm;
    float* sbias = (float*)(sm + 512);
    const uint32_t sb = smem_u32(sm);
    const uint32_t st0 = sb + 1024, st1 = sb + 1024 + 32768;
    const uint32_t mb  = sb + 1024 + 65536;

    const int tid = threadIdx.x, wid = tid >> 5, lid = tid & 31;
    const int wm = wid & 1, wn = wid >> 1;
    const int mt = blockIdx.y, nb0 = blockIdx.x * 128;

    const char* Atl = (const char*)((PHASE == 1) ? (const void*)g_af : (const void*)g_ff)
                    + (((size_t)mt * NC) << 14);
    const char* Btl = (const char*)((PHASE == 1) ? (const void*)g_w1t : (const void*)g_w2t)
                    + (((size_t)blockIdx.x * NC) << 14);

    if (tid < 128) {
        sbias[tid] = bias[nb0 + tid];
        if (PHASE == 2) sseq[tid] = seq[mt * 128 + tid];
    }
    if (tid == 0) { MBAR_INIT(mb, 1); MBAR_INIT(mb + 8, 1); }
    __syncthreads();

    if (tid == 0) {
        MBAR_TX(mb, 32768);
        BULK(st0, Atl, 16384, mb);
        BULK(st0 + 16384, Btl, 16384, mb);
        MBAR_TX(mb + 8, 32768);
        BULK(st1, Atl + 16384, 16384, mb + 8);
        BULK(st1 + 16384, Btl + 16384, 16384, mb + 8);
    }

    float acc[4][4][4];
    #pragma unroll
    for (int a = 0; a < 4; ++a)
        #pragma unroll
        for (int b = 0; b < 4; ++b)
            #pragma unroll
            for (int c = 0; c < 4; ++c) acc[a][b][c] = 0.f;

    for (int c = 0; c < NC; ++c) {
        int s = c & 1;
        uint32_t stg = s ? st1 : st0;
        MBAR_WAIT(mb + s * 8, (c >> 1) & 1);
        ffn_compute(stg, stg + 16384, wm, wn, lid, acc);
        __syncthreads();
        if (tid == 0 && c + 2 < NC) {
            MBAR_TX(mb + s * 8, 32768);
            BULK(stg, Atl + ((size_t)(c + 2) << 14), 16384, mb + s * 8);
            BULK(stg + 16384, Btl + ((size_t)(c + 2) << 14), 16384, mb + s * 8);
        }
    }

    const int qm = lid >> 2, qn = (lid & 3) * 2;
    if (PHASE == 1) {
        uint32_t* SH = (uint32_t*)(sm + 1024);
        #pragma unroll
        for (int mf = 0; mf < 4; ++mf)
            #pragma unroll
            for (int nf = 0; nf < 2; ++nf)
                #pragma unroll
                for (int j = 0; j < 2; ++j) {
                    const float* d = acc[mf][nf*2+j];
                    int nl = wn * 32 + nf * 16 + j * 8 + qn;
                    #pragma unroll
                    for (int hh = 0; hh < 2; ++hh) {
                        int ml = wm * 64 + mf * 16 + qm + hh * 8;
                        float v0 = fmaxf(d[hh*2+0] + sbias[nl],   0.f);
                        float v1 = fmaxf(d[hh*2+1] + sbias[nl+1], 0.f);
                        SH[ml * 64 + (nl >> 1)] = packh2(v0, v1);
                    }
                }
        __syncthreads();
        char* gff = (char*)g_ff;
        #pragma unroll
        for (int t = 0; t < 8; ++t) {
            int idx = t * 256 + tid;
            int tile = idx >> 10, rem = idx & 1023;
            int r = rem >> 3, j = rem & 7;
            uint4 v = ((const uint4*)SH)[r * 16 + tile * 8 + j];
            size_t off = (((size_t)mt * 8 + blockIdx.x * 2 + tile) << 14)
                       + SWZ((uint32_t)(r * 128 + j * 16));
            *(uint4*)(gff + off) = v;
        }
    } else {
        float* SF = (float*)(sm + 1024);
        #pragma unroll
        for (int mf = 0; mf < 4; ++mf)
            #pragma unroll
            for (int nf = 0; nf < 2; ++nf)
                #pragma unroll
                for (int j = 0; j < 2; ++j) {
                    const float* d = acc[mf][nf*2+j];
                    int nl = wn * 32 + nf * 16 + j * 8 + qn;
                    #pragma unroll
                    for (int hh = 0; hh < 2; ++hh) {
                        int ml = wm * 64 + mf * 16 + qm + hh * 8;
                        SF[ml * 128 + nl]     = d[hh*2+0] + sbias[nl];
                        SF[ml * 128 + nl + 1] = d[hh*2+1] + sbias[nl+1];
                    }
                }
        __syncthreads();
        int row = tid >> 1, part = tid & 1;
        int tok = sseq[row];
        const float4* ep = (const float4*)(embed + (size_t)tok * HH + nb0);
        const float4* sfp = (const float4*)(SF + row * 128);
        float4* gp = (float4*)(g_h + ((size_t)mt * 128 + row) * HH + nb0);
        #pragma unroll
        for (int j = 0; j < 16; ++j) {
            int c4 = part * 16 + j;
            float4 f = sfp[c4];
            float4 e = ep[c4];
            f.x += e.x; f.y += e.y; f.z += e.z; f.w += e.w;
            gp[c4] = f;
        }
    }
}

// ---------------- 3. LayerNorm: one warp per row; also emit fp16 swz5 K tiles ----------------
__global__ void k_ln(const float* __restrict__ gamma, const float* __restrict__ beta_ln) {
    int warp = threadIdx.x >> 5, lane = threadIdx.x & 31;
    size_t row = (size_t)blockIdx.x * 8 + warp;
    int bb = (int)(row >> 11), l = (int)(row & 2047);
    float4* xp = (float4*)(g_h + row * HH);
    float4 a = xp[lane * 2];
    float4 b = xp[lane * 2 + 1];
    float s = a.x + a.y + a.z + a.w + b.x + b.y + b.z + b.w;
    #pragma unroll
    for (int o = 16; o; o >>= 1) s += __shfl_xor_sync(0xffffffffu, s, o);
    float mu = s * (1.0f / HH);
    float dx[8] = {a.x-mu, a.y-mu, a.z-mu, a.w-mu, b.x-mu, b.y-mu, b.z-mu, b.w-mu};
    float v = 0.f;
    #pragma unroll
    for (int q = 0; q < 8; ++q) v += dx[q] * dx[q];
    #pragma unroll
    for (int o = 16; o; o >>= 1) v += __shfl_xor_sync(0xffffffffu, v, o);
    float inv = rsqrtf(v * (1.0f / HH) + 1e-5f);
    float4 g0 = ((const float4*)gamma)[lane * 2];
    float4 g1 = ((const float4*)gamma)[lane * 2 + 1];
    float4 t0 = ((const float4*)beta_ln)[lane * 2];
    float4 t1 = ((const float4*)beta_ln)[lane * 2 + 1];
    float4 o0, o1;
    o0.x = dx[0]*inv*g0.x + t0.x; o0.y = dx[1]*inv*g0.y + t0.y;
    o0.z = dx[2]*inv*g0.z + t0.z; o0.w = dx[3]*inv*g0.w + t0.w;
    o1.x = dx[4]*inv*g1.x + t1.x; o1.y = dx[5]*inv*g1.y + t1.y;
    o1.z = dx[6]*inv*g1.z + t1.z; o1.w = dx[7]*inv*g1.w + t1.w;
    xp[lane * 2]     = o0;
    xp[lane * 2 + 1] = o1;
    // fp16 swizzled tile copy for the scan's K (token 2047 = pad row, zeros)
    uint4 hv = (l == 2047) ? make_uint4(0, 0, 0, 0)
             : make_uint4(packh2(o0.x, o0.y), packh2(o0.z, o0.w),
                          packh2(o1.x, o1.y), packh2(o1.z, o1.w));
    size_t toff = (((size_t)bb * NCH + (l >> 5)) << 14)
                + SWZ5((uint32_t)((l & 31) * 512 + lane * 16));
    *(uint4*)((char*)g_hh + toff) = hv;
}

// ---------------- 4. scan: fp16 HMMA, K via double-buffered cp.async.bulk ----------------
static constexpr uint32_t OFF_MH  = 0;        // [128][512B] fp16 swz5
static constexpr uint32_t OFF_K0  = 65536;    // KH buffer 0 (16KB)
static constexpr uint32_t OFF_K1  = 81920;    // KH buffer 1
static constexpr uint32_t OFF_SD  = 98304;    // [32][128] f32 raw U
static constexpr uint32_t OFF_DT  = 114688;   // [128][80B] fp16 weighted d^T
static constexpr uint32_t OFF_G   = 124928;   // [32][36] f32
static constexpr uint32_t OFF_A   = 129536;   // [32][32] f32
static constexpr uint32_t OFF_SC  = 133632;   // sc, ct, wv, spw (1024B)
static constexpr uint32_t OFF_MB  = 134656;   // 2 mbarriers
static constexpr int SCAN_SMEM_BYTES = 134784;

__global__ __launch_bounds__(256, 1) void k_scan() {
    extern __shared__ char smc[];
    const uint32_t sb = smem_u32(smc);
    const uint32_t MH = sb + OFF_MH;
    const uint32_t mb = sb + OFF_MB;
    float* sD  = (float*)(smc + OFF_SD);
    float* sG  = (float*)(smc + OFF_G);
    float* sA  = (float*)(smc + OFF_A);
    float* sc  = (float*)(smc + OFF_SC);
    float* ct  = sc + 32;
    float* wv  = ct + 32;
    float* spw = wv + 32;

    const int tid = threadIdx.x, wid = tid >> 5, lid = tid & 31;
    const int qm = lid >> 2, qn = (lid & 3) * 2;
    const int b  = blockIdx.x >> 1;
    const int r0 = (blockIdx.x & 1) * 128;
    const float* hb = g_h + (size_t)b * LL * HH;
    const char* tiles = (const char*)g_hh + (((size_t)b * NCH) << 14);

    for (int i = tid; i < 65536 / 16; i += 256)
        ((uint4*)(smc + OFF_MH))[i] = make_uint4(0, 0, 0, 0);
    if (tid == 0) {
        spw[0] = 1.f;
        for (int i = 1; i <= CH; ++i) spw[i] = spw[i-1] * BETA;
        MBAR_INIT(mb, 1); MBAR_INIT(mb + 8, 1);
    }
    __syncthreads();
    if (tid == 0) {
        MBAR_TX(mb, 16384);
        BULK(sb + OFF_K0, tiles, 16384, mb);
    }

    float acc[32][4];
    #pragma unroll
    for (int f = 0; f < 32; ++f)
        #pragma unroll
        for (int q = 0; q < 4; ++q) acc[f][q] = 0.f;

    for (int c = 0; c < NCH; ++c) {
        const int t0 = c * CH;
        const int Cc = min(CH, TT - t0);
        __syncthreads();   // previous chunk's reads of both K buffers done

        // prefetch next chunk into the other buffer
        if (tid == 0 && c + 1 < NCH) {
            int nb = (c + 1) & 1;
            MBAR_TX(mb + nb * 8, 16384);
            BULK(sb + (nb ? OFF_K1 : OFF_K0), tiles + ((size_t)(c + 1) << 14),
                 16384, mb + nb * 8);
        }
        MBAR_WAIT(mb + (c & 1) * 8, (c >> 1) & 1);
        const uint32_t KH = sb + ((c & 1) ? OFF_K1 : OFF_K0);

        // ---- (b) Gram G = K K^T ----
        {
            float gacc[4] = {0.f, 0.f, 0.f, 0.f};
            const int mh = wid & 1, nq = wid >> 1;
            const uint32_t arow = (uint32_t)(16 * mh + (lid & 15)) * 512;
            const uint32_t asel = (uint32_t)((lid >> 4) << 4);
            const uint32_t brow = (uint32_t)(8 * nq + (lid & 7)) * 512;
            const uint32_t bsel = (uint32_t)(((lid >> 3) & 1) << 4);
            #pragma unroll
            for (int ks = 0; ks < 16; ++ks) {
                uint32_t ca = ks * 32;
                uint32_t ag[4], gb[2];
                ldsm_x4(ag, KH + SWZ5(arow + ca + asel));
                ldsm_x2(gb, KH + SWZ5(brow + ca + bsel));
                mma_f16(gacc, ag, gb[0], gb[1]);
            }
            int t = 16 * mh + qm, s = 8 * nq + qn;
            sG[t*36 + s] = gacc[0]; sG[t*36 + s + 1] = gacc[1];
            sG[(t+8)*36 + s] = gacc[2]; sG[(t+8)*36 + s + 1] = gacc[3];
        }
        __syncthreads();

        if (tid < 32) {
            float g = sG[tid*36 + tid];
            float s = 1.0f / (g + 1e-6f);
            sc[tid] = s;
            ct[tid] = s * spw[tid];
            wv[tid] = (tid < Cc) ? OMB * spw[Cc - 1 - tid] : 0.f;
        }
        __syncthreads();

        // ---- (c) coupling coefs + (d) U = M K^T ----
        for (int p = tid; p < 1024; p += 256) {
            int t = p >> 5, s = p & 31;
            if (s < t) sA[p] = sG[t*36 + s] * sc[t] * OMB * spw[t - 1 - s];
        }
        {
            float uacc[4][4];
            #pragma unroll
            for (int f = 0; f < 4; ++f)
                #pragma unroll
                for (int q = 0; q < 4; ++q) uacc[f][q] = 0.f;
            const uint32_t mrow = (uint32_t)(16 * wid + (lid & 15)) * 512;
            const uint32_t asel = (uint32_t)((lid >> 4) << 4);
            const uint32_t brow0 = (uint32_t)(((lid >> 4) << 3) + (lid & 7)) * 512;
            const uint32_t brow1 = brow0 + 16 * 512;
            const uint32_t bsel = (uint32_t)(((lid >> 3) & 1) << 4);
            #pragma unroll
            for (int ks = 0; ks < 16; ++ks) {
                uint32_t ca = ks * 32;
                uint32_t am[4], b0[4], b1[4];
                ldsm_x4(am, MH + SWZ5(mrow + ca + asel));
                ldsm_x4(b0, KH + SWZ5(brow0 + ca + bsel));
                ldsm_x4(b1, KH + SWZ5(brow1 + ca + bsel));
                #pragma unroll
                for (int f = 0; f < 4; ++f) {
                    const uint32_t* bh = (f < 2) ? b0 : b1;
                    int j = (f & 1) * 2;
                    mma_f16(uacc[f], am, bh[j], bh[j+1]);
                }
            }
            int i = 16 * wid + qm;
            #pragma unroll
            for (int f = 0; f < 4; ++f) {
                int lt = 8 * f + qn;
                sD[lt*128 + i]           = uacc[f][0];
                sD[(lt+1)*128 + i]       = uacc[f][1];
                sD[lt*128 + i + 8]       = uacc[f][2];
                sD[(lt+1)*128 + i + 8]   = uacc[f][3];
            }
        }
        __syncthreads();

        // ---- (e) triangular solve; rhs = fp32 h from global ----
        if (tid < 128) {
            const int i = tid;
            float d[CH];
            #pragma unroll
            for (int t = 0; t < CH; ++t) {
                float rhs = (t < Cc) ? hb[(size_t)(t0 + t) * HH + r0 + i] : 0.f;
                d[t] = rhs - ct[t] * sD[t*128 + i];
            }
            #pragma unroll
            for (int s = 0; s < CH - 1; ++s)
                #pragma unroll
                for (int t = s + 1; t < CH; ++t)
                    d[t] -= sA[t*32 + s] * d[s];
            #pragma unroll
            for (int s = 0; s < CH; s += 2)
                *(uint32_t*)(smc + OFF_DT + i*80 + s*2) =
                    packh2(d[s] * wv[s], d[s+1] * wv[s+1]);
        }
        __syncthreads();

        // ---- (f) M update: acc = beta^Cc * acc + dT^T @ K ----
        {
            float bc = spw[Cc];
            #pragma unroll
            for (int f = 0; f < 32; ++f)
                #pragma unroll
                for (int q = 0; q < 4; ++q) acc[f][q] *= bc;
            const uint32_t adbase = (uint32_t)(16 * wid + (lid & 15)) * 80
                                  + (uint32_t)((lid >> 4) << 4);
            const uint32_t tsel = (uint32_t)((lid >> 4) << 3) * 2;
            #pragma unroll
            for (int ks = 0; ks < 2; ++ks) {
                uint32_t ad[4];
                ldsm_x4(ad, sb + OFF_DT + adbase + ks * 32);
                uint32_t trow = (uint32_t)(ks * 16 + (lid & 15)) * 512;
                #pragma unroll
                for (int jg = 0; jg < 16; ++jg) {
                    uint32_t o = SWZ5(trow + jg * 32 + tsel);
                    uint32_t bt[4];
                    ldsm_x4t(bt, KH + o);
                    mma_f16(acc[jg*2],   ad, bt[0], bt[1]);
                    mma_f16(acc[jg*2+1], ad, bt[2], bt[3]);
                }
            }
        }

        // ---- (g) publish M fp16 for next chunk ----
        if (c + 1 < NCH) {
            int r1 = 16 * wid + qm;
            #pragma unroll
            for (int f = 0; f < 32; ++f) {
                int cc = f * 8 + qn;
                *(uint32_t*)(smc + OFF_MH + SWZ5((uint32_t)(r1 * 512 + cc * 2))) =
                    packh2(acc[f][0], acc[f][1]);
                *(uint32_t*)(smc + OFF_MH + SWZ5((uint32_t)((r1 + 8) * 512 + cc * 2))) =
                    packh2(acc[f][2], acc[f][3]);
            }
        }
    }

    // ---- final: stage fp32 M, write g_M ----
    __syncthreads();
    {
        float* SF = (float*)smc;
        int r1 = 16 * wid + qm;
        #pragma unroll
        for (int f = 0; f < 32; ++f) {
            int c = f * 8 + qn;
            SF[r1*256 + c]       = acc[f][0];
            SF[r1*256 + c + 1]   = acc[f][1];
            SF[(r1+8)*256 + c]   = acc[f][2];
            SF[(r1+8)*256 + c+1] = acc[f][3];
        }
        __syncthreads();
        const float4* sp = (const float4*)SF;
        for (int q = tid; q < 128 * 64; q += 256) {
            int i = q >> 6, j4 = q & 63;
            ((float4*)(g_M + ((size_t)b * HH + r0 + i) * HH))[j4] = sp[i*64 + j4];
        }
    }
}

// ---------------- 5-7. readout ----------------
__global__ void k_read1() {
    int b = blockIdx.x;
    int tid = threadIdx.x;
    __shared__ float hl[HH];
    hl[tid] = g_h[((size_t)b * LL + (LL - 1)) * HH + tid];
    __syncthreads();
    int w = tid >> 5, lane = tid & 31;
    for (int i = w; i < HH; i += 8) {
        const float* Mr = g_M + ((size_t)b * HH + i) * HH;
        float s = 0.f;
        #pragma unroll
        for (int j = lane; j < HH; j += 32) s += Mr[j] * hl[j];
        #pragma unroll
        for (int o = 16; o; o >>= 1) s += __shfl_xor_sync(0xffffffffu, s, o);
        if (lane == 0) g_y[b * HH + i] = s;
    }
}
__global__ void k_read2(const float* __restrict__ rp_W, const float* __restrict__ rp_b) {
    int b = blockIdx.x, n = threadIdx.x;
    __shared__ float ys[HH];
    ys[n] = g_y[b * HH + n];
    __syncthreads();
    float acc = rp_b[n];
    #pragma unroll 4
    for (int k = 0; k < HH; ++k) acc += ys[k] * rp_W[k * HH + n];
    g_y2[b * HH + n] = acc;
}

static constexpr int OUT_SMEM_BYTES = (HH * 128 + BB * 257) * 4;

__global__ __launch_bounds__(256) void k_out(
    const float* __restrict__ out_W, const float* __restrict__ out_b,
    float* __restrict__ out)
{
    extern __shared__ float smf[];
    float* sW  = smf;
    float* sy2 = smf + HH * 128;
    int tid = threadIdx.x;
    int n_base = blockIdx.x * 128;

    for (int idx = tid; idx < HH * 32; idx += 256) {
        int k = idx >> 5, q = idx & 31;
        *(float4*)(sW + k*128 + q*4) = *(const float4*)(out_W + (size_t)k * VV + n_base + q*4);
    }
    for (int idx = tid; idx < BB * 64; idx += 256) {
        int bb = idx >> 6, q = idx & 63;
        float4 v = *(const float4*)(g_y2 + bb * HH + q*4);
        float* d = sy2 + bb*257 + q*4;
        d[0] = v.x; d[1] = v.y; d[2] = v.z; d[3] = v.w;
    }
    __syncthreads();

    int bg = tid >> 4, ng = tid & 15;
    int b0 = bg * 4, n0 = ng * 8;
    float acc[4][8];
    #pragma unroll
    for (int r = 0; r < 4; ++r)
        #pragma unroll
        for (int c = 0; c < 8; ++c) acc[r][c] = 0.f;
    for (int k = 0; k < HH; ++k) {
        float4 w0 = *(const float4*)(sW + k*128 + n0);
        float4 w1 = *(const float4*)(sW + k*128 + n0 + 4);
        float wv[8] = {w0.x, w0.y, w0.z, w0.w, w1.x, w1.y, w1.z, w1.w};
        #pragma unroll
        for (int r = 0; r < 4; ++r) {
            float yv = sy2[(b0+r)*257 + k];
            #pragma unroll
            for (int c = 0; c < 8; ++c) acc[r][c] += yv * wv[c];
        }
    }
    #pragma unroll
    for (int r = 0; r < 4; ++r)
        #pragma unroll
        for (int c = 0; c < 8; ++c)
            out[(size_t)(b0+r) * VV + n_base + n0 + c] = acc[r][c] + out_b[n_base + n0 + c];
}

// ---------------- launch ----------------
extern "C" void kernel_launch(void* const* d_in, const int* in_sizes, int n_in,
                              void* d_out, int out_size) {
    (void)in_sizes; (void)n_in; (void)out_size;
    const int*   seq     = (const int*)  d_in[0];
    const float* embed   = (const float*)d_in[1];
    const float* W1      = (const float*)d_in[2];
    const float* b1      = (const float*)d_in[3];
    const float* W2      = (const float*)d_in[4];
    const float* b2      = (const float*)d_in[5];
    const float* gamma   = (const float*)d_in[6];
    const float* beta_ln = (const float*)d_in[7];
    const float* rp_W    = (const float*)d_in[8];
    const float* rp_b    = (const float*)d_in[9];
    const float* out_W   = (const float*)d_in[10];
    const float* out_b   = (const float*)d_in[11];
    float* out = (float*)d_out;

    cudaFuncSetAttribute(k_ffn<1>, cudaFuncAttributeMaxDynamicSharedMemorySize, FFN_SMEM);
    cudaFuncSetAttribute(k_ffn<2>, cudaFuncAttributeMaxDynamicSharedMemorySize, FFN_SMEM);
    cudaFuncSetAttribute(k_scan,   cudaFuncAttributeMaxDynamicSharedMemorySize, SCAN_SMEM_BYTES);
    cudaFuncSetAttribute(k_out,    cudaFuncAttributeMaxDynamicSharedMemorySize, OUT_SMEM_BYTES);

    k_prep<<<512, 256>>>(W1, W2);
    k_split<<<BB * LL * 32 / 256, 256>>>(seq, embed);
    k_ffn<1><<<dim3(4, BB*LL/128), 256, FFN_SMEM>>>(seq, embed, b1);
    k_ffn<2><<<dim3(2, BB*LL/128), 256, FFN_SMEM>>>(seq, embed, b2);
    k_ln<<<BB * LL / 8, 256>>>(gamma, beta_ln);
    k_scan<<<BB * 2, 256, SCAN_SMEM_BYTES>>>();
    k_read1<<<BB, 256>>>();
    k_read2<<<BB, HH>>>(rp_W, rp_b);
    k_out<<<VV / 128, 256, OUT_SMEM_BYTES>>>(out_W, out_b, out);
}

// round 17
// speedup vs baseline: 1.6235x; 1.0729x over previous
#include <cuda_runtime.h>
#include <cuda_fp16.h>
#include <math.h>
#include <stdint.h>

static constexpr int BB = 64;
static constexpr int LL = 2048;
static constexpr int HH = 256;
static constexpr int VV = 32000;
static constexpr int TT = LL - 1;
static constexpr float BETA = 0.9f;
static constexpr float OMB  = 0.1f;
static constexpr int CH = 32;
static constexpr int NCH = 64;

// ---------------- scratch ----------------
__device__ float  g_h [(size_t)BB*LL*HH];       // x (UN-normalized)
__device__ __half g_hh[(size_t)BB*LL*HH];       // LN(x) fp16 swz5 16KB tiles
__device__ __half g_af[(size_t)BB*LL*HH];
__device__ __half g_ff[(size_t)BB*LL*2*HH];
__device__ __half g_w1t[512*256];
__device__ __half g_w2t[256*512];
__device__ float  g_M [(size_t)BB*HH*HH];
__device__ float  g_y [BB*HH];
__device__ float  g_y2[BB*HH];

#define SWZ(o)  ((o) ^ (((o) >> 3) & 0x70))
#define SWZ5(o) ((o) ^ (((o) >> 5) & 0x70))

__device__ __forceinline__ uint32_t smem_u32(const void* p) {
    uint32_t a;
    asm("{ .reg .u64 t; cvta.to.shared.u64 t, %1; cvt.u32.u64 %0, t; }" : "=r"(a) : "l"(p));
    return a;
}
__device__ __forceinline__ uint32_t packh2(float a, float b) {
    __half2 t = __floats2half2_rn(a, b);
    return *reinterpret_cast<uint32_t*>(&t);
}
__device__ __forceinline__ void ldsm_x4(uint32_t* r, uint32_t addr) {
    asm volatile("ldmatrix.sync.aligned.m8n8.x4.shared.b16 {%0,%1,%2,%3}, [%4];"
        : "=r"(r[0]), "=r"(r[1]), "=r"(r[2]), "=r"(r[3]) : "r"(addr));
}
__device__ __forceinline__ void ldsm_x4t(uint32_t* r, uint32_t addr) {
    asm volatile("ldmatrix.sync.aligned.m8n8.x4.trans.shared.b16 {%0,%1,%2,%3}, [%4];"
        : "=r"(r[0]), "=r"(r[1]), "=r"(r[2]), "=r"(r[3]) : "r"(addr));
}
__device__ __forceinline__ void ldsm_x2(uint32_t* r, uint32_t addr) {
    asm volatile("ldmatrix.sync.aligned.m8n8.x2.shared.b16 {%0,%1}, [%2];"
        : "=r"(r[0]), "=r"(r[1]) : "r"(addr));
}
__device__ __forceinline__ void mma_f16(float* d, const uint32_t* a, uint32_t b0, uint32_t b1) {
    asm volatile("mma.sync.aligned.m16n8k16.row.col.f32.f16.f16.f32 "
        "{%0,%1,%2,%3}, {%4,%5,%6,%7}, {%8,%9}, {%0,%1,%2,%3};"
        : "+f"(d[0]), "+f"(d[1]), "+f"(d[2]), "+f"(d[3])
        : "r"(a[0]), "r"(a[1]), "r"(a[2]), "r"(a[3]), "r"(b0), "r"(b1));
}

#define MBAR_INIT(a, cnt) \
    asm volatile("mbarrier.init.shared.b64 [%0], %1;" :: "r"((uint32_t)(a)), "r"((uint32_t)(cnt)) : "memory")
#define MBAR_TX(a, bytes) \
    asm volatile("mbarrier.arrive.expect_tx.shared.b64 _, [%0], %1;" :: "r"((uint32_t)(a)), "r"((uint32_t)(bytes)) : "memory")
#define BULK(dst, src, bytes, mbar) \
    asm volatile("cp.async.bulk.shared::cta.global.mbarrier::complete_tx::bytes [%0], [%1], %2, [%3];" \
        :: "r"((uint32_t)(dst)), "l"(src), "r"((uint32_t)(bytes)), "r"((uint32_t)(mbar)) : "memory")
#define MBAR_WAIT(a, par) do {                                                    \
    uint32_t _m = (uint32_t)(a); uint32_t _p = (uint32_t)(par); uint32_t _d;      \
    asm volatile("{\n\t.reg .pred p;\n\t"                                         \
        "mbarrier.try_wait.parity.acquire.cta.shared::cta.b64 p, [%1], %2;\n\t"   \
        "selp.b32 %0, 1, 0, p;\n\t}"                                              \
        : "=r"(_d) : "r"(_m), "r"(_p) : "memory");                                \
    if (!_d) {                                                                    \
        asm volatile("{\n\t.reg .pred P1;\n\t"                                    \
            "WL_%=:\n\t"                                                          \
            "mbarrier.try_wait.parity.acquire.cta.shared::cta.b64 P1, [%0], %1, 0x989680;\n\t" \
            "@P1 bra.uni WD_%=;\n\t"                                              \
            "bra.uni WL_%=;\n\t"                                                  \
            "WD_%=:\n\t}"                                                         \
            :: "r"(_m), "r"(_p) : "memory");                                      \
    }                                                                             \
} while (0)

// ---------------- 0a. weights -> fp16, tiled-swizzled 16KB tiles ----------------
__global__ void k_prep(const float* __restrict__ W1, const float* __restrict__ W2) {
    int idx = blockIdx.x * blockDim.x + threadIdx.x;
    {
        int n = idx >> 8, k = idx & 255;
        __half v = __float2half_rn(W1[k * 512 + n]);
        size_t off = (((size_t)(n >> 7) * 4 + (k >> 6)) << 14)
                   + SWZ((uint32_t)((n & 127) * 128 + (k & 63) * 2));
        *(__half*)((char*)g_w1t + off) = v;
    }
    {
        int n = idx >> 9, k = idx & 511;
        __half v = __float2half_rn(W2[k * 256 + n]);
        size_t off = (((size_t)(n >> 7) * 8 + (k >> 6)) << 14)
                   + SWZ((uint32_t)((n & 127) * 128 + (k & 63) * 2));
        *(__half*)((char*)g_w2t + off) = v;
    }
}

// ---------------- 0b. gather -> fp16 tiled-swizzled ----------------
__global__ void k_split(const int* __restrict__ seq, const float* __restrict__ embed) {
    size_t idx = (size_t)blockIdx.x * blockDim.x + threadIdx.x;
    int row = (int)(idx >> 5), g = (int)(idx & 31);
    int tok = seq[row];
    const float4* src = (const float4*)(embed + (size_t)tok * HH + g * 8);
    float4 v0 = src[0], v1 = src[1];
    uint4 o = make_uint4(packh2(v0.x, v0.y), packh2(v0.z, v0.w),
                         packh2(v1.x, v1.y), packh2(v1.z, v1.w));
    int mt = row >> 7, c = g >> 3;
    size_t off = (((size_t)mt * 4 + c) << 14)
               + SWZ((uint32_t)((row & 127) * 128 + (g & 7) * 16));
    *(uint4*)((char*)g_af + off) = o;
}

// ---------------- 1+2. FFN: fp16 HMMA + cp.async.bulk 2-stage ----------------
static constexpr int FFN_SMEM = 1024 + 65536 + 64;

__device__ __forceinline__ void ffn_compute(uint32_t aB, uint32_t bB,
                                            int wm, int wn, int lid, float (&acc)[4][4][4])
{
    #pragma unroll
    for (int ks = 0; ks < 4; ++ks) {
        uint32_t colA = ks * 32 + ((lid >> 4) << 4);
        uint32_t ah[4][4];
        #pragma unroll
        for (int mf = 0; mf < 4; ++mf) {
            uint32_t row = wm * 64 + mf * 16 + (lid & 15);
            ldsm_x4(ah[mf], aB + SWZ(row * 128 + colA));
        }
        uint32_t bh[2][4];
        #pragma unroll
        for (int nf = 0; nf < 2; ++nf) {
            uint32_t row = wn * 32 + nf * 16 + ((lid >> 4) << 3) + (lid & 7);
            uint32_t colB = ks * 32 + (((lid >> 3) & 1) << 4);
            ldsm_x4(bh[nf], bB + SWZ(row * 128 + colB));
        }
        #pragma unroll
        for (int mf = 0; mf < 4; ++mf)
            #pragma unroll
            for (int nf = 0; nf < 2; ++nf)
                #pragma unroll
                for (int j = 0; j < 2; ++j)
                    mma_f16(acc[mf][nf*2+j], ah[mf], bh[nf][j*2], bh[nf][j*2+1]);
    }
}

template<int PHASE>
__global__ __launch_bounds__(256, 2) void k_ffn(
    const int* __restrict__ seq, const float* __restrict__ embed,
    const float* __restrict__ bias)
{
    constexpr int NC = (PHASE == 1) ? 4 : 8;

    extern __shared__ char sm[];
    int*   sseq  = (int*)sm;
    float* sbias = (float*)(sm + 512);
    const uint32_t sb = smem_u32(sm);
    const uint32_t st0 = sb + 1024, st1 = sb + 1024 + 32768;
    const uint32_t mb  = sb + 1024 + 65536;

    const int tid = threadIdx.x, wid = tid >> 5, lid = tid & 31;
    const int wm = wid & 1, wn = wid >> 1;
    const int mt = blockIdx.y, nb0 = blockIdx.x * 128;

    const char* Atl = (const char*)((PHASE == 1) ? (const void*)g_af : (const void*)g_ff)
                    + (((size_t)mt * NC) << 14);
    const char* Btl = (const char*)((PHASE == 1) ? (const void*)g_w1t : (const void*)g_w2t)
                    + (((size_t)blockIdx.x * NC) << 14);

    if (tid < 128) {
        sbias[tid] = bias[nb0 + tid];
        if (PHASE == 2) sseq[tid] = seq[mt * 128 + tid];
    }
    if (tid == 0) { MBAR_INIT(mb, 1); MBAR_INIT(mb + 8, 1); }
    __syncthreads();

    if (tid == 0) {
        MBAR_TX(mb, 32768);
        BULK(st0, Atl, 16384, mb);
        BULK(st0 + 16384, Btl, 16384, mb);
        MBAR_TX(mb + 8, 32768);
        BULK(st1, Atl + 16384, 16384, mb + 8);
        BULK(st1 + 16384, Btl + 16384, 16384, mb + 8);
    }

    float acc[4][4][4];
    #pragma unroll
    for (int a = 0; a < 4; ++a)
        #pragma unroll
        for (int b = 0; b < 4; ++b)
            #pragma unroll
            for (int c = 0; c < 4; ++c) acc[a][b][c] = 0.f;

    for (int c = 0; c < NC; ++c) {
        int s = c & 1;
        uint32_t stg = s ? st1 : st0;
        MBAR_WAIT(mb + s * 8, (c >> 1) & 1);
        ffn_compute(stg, stg + 16384, wm, wn, lid, acc);
        __syncthreads();
        if (tid == 0 && c + 2 < NC) {
            MBAR_TX(mb + s * 8, 32768);
            BULK(stg, Atl + ((size_t)(c + 2) << 14), 16384, mb + s * 8);
            BULK(stg + 16384, Btl + ((size_t)(c + 2) << 14), 16384, mb + s * 8);
        }
    }

    const int qm = lid >> 2, qn = (lid & 3) * 2;
    if (PHASE == 1) {
        uint32_t* SH = (uint32_t*)(sm + 1024);
        #pragma unroll
        for (int mf = 0; mf < 4; ++mf)
            #pragma unroll
            for (int nf = 0; nf < 2; ++nf)
                #pragma unroll
                for (int j = 0; j < 2; ++j) {
                    const float* d = acc[mf][nf*2+j];
                    int nl = wn * 32 + nf * 16 + j * 8 + qn;
                    #pragma unroll
                    for (int hh = 0; hh < 2; ++hh) {
                        int ml = wm * 64 + mf * 16 + qm + hh * 8;
                        float v0 = fmaxf(d[hh*2+0] + sbias[nl],   0.f);
                        float v1 = fmaxf(d[hh*2+1] + sbias[nl+1], 0.f);
                        SH[ml * 64 + (nl >> 1)] = packh2(v0, v1);
                    }
                }
        __syncthreads();
        char* gff = (char*)g_ff;
        #pragma unroll
        for (int t = 0; t < 8; ++t) {
            int idx = t * 256 + tid;
            int tile = idx >> 10, rem = idx & 1023;
            int r = rem >> 3, j = rem & 7;
            uint4 v = ((const uint4*)SH)[r * 16 + tile * 8 + j];
            size_t off = (((size_t)mt * 8 + blockIdx.x * 2 + tile) << 14)
                       + SWZ((uint32_t)(r * 128 + j * 16));
            *(uint4*)(gff + off) = v;
        }
    } else {
        float* SF = (float*)(sm + 1024);
        #pragma unroll
        for (int mf = 0; mf < 4; ++mf)
            #pragma unroll
            for (int nf = 0; nf < 2; ++nf)
                #pragma unroll
                for (int j = 0; j < 2; ++j) {
                    const float* d = acc[mf][nf*2+j];
                    int nl = wn * 32 + nf * 16 + j * 8 + qn;
                    #pragma unroll
                    for (int hh = 0; hh < 2; ++hh) {
                        int ml = wm * 64 + mf * 16 + qm + hh * 8;
                        SF[ml * 128 + nl]     = d[hh*2+0] + sbias[nl];
                        SF[ml * 128 + nl + 1] = d[hh*2+1] + sbias[nl+1];
                    }
                }
        __syncthreads();
        int row = tid >> 1, part = tid & 1;
        int tok = sseq[row];
        const float4* ep = (const float4*)(embed + (size_t)tok * HH + nb0);
        const float4* sfp = (const float4*)(SF + row * 128);
        float4* gp = (float4*)(g_h + ((size_t)mt * 128 + row) * HH + nb0);
        #pragma unroll
        for (int j = 0; j < 16; ++j) {
            int c4 = part * 16 + j;
            float4 f = sfp[c4];
            float4 e = ep[c4];
            f.x += e.x; f.y += e.y; f.z += e.z; f.w += e.w;
            gp[c4] = f;
        }
    }
}

// ---------------- 3. LayerNorm: read x, emit ONLY fp16 swz5 K tiles ----------------
__global__ void k_ln(const float* __restrict__ gamma, const float* __restrict__ beta_ln) {
    int warp = threadIdx.x >> 5, lane = threadIdx.x & 31;
    size_t row = (size_t)blockIdx.x * 8 + warp;
    int bb = (int)(row >> 11), l = (int)(row & 2047);
    const float4* xp = (const float4*)(g_h + row * HH);
    float4 a = xp[lane * 2];
    float4 b = xp[lane * 2 + 1];
    float s = a.x + a.y + a.z + a.w + b.x + b.y + b.z + b.w;
    #pragma unroll
    for (int o = 16; o; o >>= 1) s += __shfl_xor_sync(0xffffffffu, s, o);
    float mu = s * (1.0f / HH);
    float dx[8] = {a.x-mu, a.y-mu, a.z-mu, a.w-mu, b.x-mu, b.y-mu, b.z-mu, b.w-mu};
    float v = 0.f;
    #pragma unroll
    for (int q = 0; q < 8; ++q) v += dx[q] * dx[q];
    #pragma unroll
    for (int o = 16; o; o >>= 1) v += __shfl_xor_sync(0xffffffffu, v, o);
    float inv = rsqrtf(v * (1.0f / HH) + 1e-5f);
    float4 g0 = ((const float4*)gamma)[lane * 2];
    float4 g1 = ((const float4*)gamma)[lane * 2 + 1];
    float4 t0 = ((const float4*)beta_ln)[lane * 2];
    float4 t1 = ((const float4*)beta_ln)[lane * 2 + 1];
    float f0 = dx[0]*inv*g0.x + t0.x, f1 = dx[1]*inv*g0.y + t0.y;
    float f2 = dx[2]*inv*g0.z + t0.z, f3 = dx[3]*inv*g0.w + t0.w;
    float f4 = dx[4]*inv*g1.x + t1.x, f5 = dx[5]*inv*g1.y + t1.y;
    float f6 = dx[6]*inv*g1.z + t1.z, f7 = dx[7]*inv*g1.w + t1.w;
    uint4 hv = (l == 2047) ? make_uint4(0, 0, 0, 0)
             : make_uint4(packh2(f0, f1), packh2(f2, f3),
                          packh2(f4, f5), packh2(f6, f7));
    size_t toff = (((size_t)bb * NCH + (l >> 5)) << 14)
                + SWZ5((uint32_t)((l & 31) * 512 + lane * 16));
    *(uint4*)((char*)g_hh + toff) = hv;
}

// ---------------- 4. scan: fp16 HMMA, K via double-buffered cp.async.bulk ----------------
static constexpr uint32_t OFF_MH  = 0;
static constexpr uint32_t OFF_K0  = 65536;
static constexpr uint32_t OFF_K1  = 81920;
static constexpr uint32_t OFF_SD  = 98304;
static constexpr uint32_t OFF_DT  = 114688;
static constexpr uint32_t OFF_G   = 124928;
static constexpr uint32_t OFF_A   = 129536;
static constexpr uint32_t OFF_SC  = 133632;
static constexpr uint32_t OFF_MB  = 134656;
static constexpr int SCAN_SMEM_BYTES = 134784;

__global__ __launch_bounds__(256, 1) void k_scan() {
    extern __shared__ char smc[];
    const uint32_t sb = smem_u32(smc);
    const uint32_t MH = sb + OFF_MH;
    const uint32_t mb = sb + OFF_MB;
    float* sD  = (float*)(smc + OFF_SD);
    float* sG  = (float*)(smc + OFF_G);
    float* sA  = (float*)(smc + OFF_A);
    float* sc  = (float*)(smc + OFF_SC);
    float* ct  = sc + 32;
    float* wv  = ct + 32;
    float* spw = wv + 32;

    const int tid = threadIdx.x, wid = tid >> 5, lid = tid & 31;
    const int qm = lid >> 2, qn = (lid & 3) * 2;
    const int b  = blockIdx.x >> 1;
    const int r0 = (blockIdx.x & 1) * 128;
    const char* tiles = (const char*)g_hh + (((size_t)b * NCH) << 14);

    for (int i = tid; i < 65536 / 16; i += 256)
        ((uint4*)(smc + OFF_MH))[i] = make_uint4(0, 0, 0, 0);
    if (tid == 0) {
        spw[0] = 1.f;
        for (int i = 1; i <= CH; ++i) spw[i] = spw[i-1] * BETA;
        MBAR_INIT(mb, 1); MBAR_INIT(mb + 8, 1);
    }
    __syncthreads();
    if (tid == 0) {
        MBAR_TX(mb, 16384);
        BULK(sb + OFF_K0, tiles, 16384, mb);
    }

    float acc[32][4];
    #pragma unroll
    for (int f = 0; f < 32; ++f)
        #pragma unroll
        for (int q = 0; q < 4; ++q) acc[f][q] = 0.f;

    for (int c = 0; c < NCH; ++c) {
        const int t0 = c * CH;
        const int Cc = min(CH, TT - t0);
        __syncthreads();

        if (tid == 0 && c + 1 < NCH) {
            int nb = (c + 1) & 1;
            MBAR_TX(mb + nb * 8, 16384);
            BULK(sb + (nb ? OFF_K1 : OFF_K0), tiles + ((size_t)(c + 1) << 14),
                 16384, mb + nb * 8);
        }
        MBAR_WAIT(mb + (c & 1) * 8, (c >> 1) & 1);
        const uint32_t KHOFF = (c & 1) ? OFF_K1 : OFF_K0;
        const uint32_t KH = sb + KHOFF;

        // ---- (b) Gram G = K K^T ----
        {
            float gacc[4] = {0.f, 0.f, 0.f, 0.f};
            const int mh = wid & 1, nq = wid >> 1;
            const uint32_t arow = (uint32_t)(16 * mh + (lid & 15)) * 512;
            const uint32_t asel = (uint32_t)((lid >> 4) << 4);
            const uint32_t brow = (uint32_t)(8 * nq + (lid & 7)) * 512;
            const uint32_t bsel = (uint32_t)(((lid >> 3) & 1) << 4);
            #pragma unroll
            for (int ks = 0; ks < 16; ++ks) {
                uint32_t ca = ks * 32;
                uint32_t ag[4], gb[2];
                ldsm_x4(ag, KH + SWZ5(arow + ca + asel));
                ldsm_x2(gb, KH + SWZ5(brow + ca + bsel));
                mma_f16(gacc, ag, gb[0], gb[1]);
            }
            int t = 16 * mh + qm, s = 8 * nq + qn;
            sG[t*36 + s] = gacc[0]; sG[t*36 + s + 1] = gacc[1];
            sG[(t+8)*36 + s] = gacc[2]; sG[(t+8)*36 + s + 1] = gacc[3];
        }
        __syncthreads();

        if (tid < 32) {
            float g = sG[tid*36 + tid];
            float s = 1.0f / (g + 1e-6f);
            sc[tid] = s;
            ct[tid] = s * spw[tid];
            wv[tid] = (tid < Cc) ? OMB * spw[Cc - 1 - tid] : 0.f;
        }
        __syncthreads();

        // ---- (c) coupling coefs + (d) U = M K^T ----
        for (int p = tid; p < 1024; p += 256) {
            int t = p >> 5, s = p & 31;
            if (s < t) sA[p] = sG[t*36 + s] * sc[t] * OMB * spw[t - 1 - s];
        }
        {
            float uacc[4][4];
            #pragma unroll
            for (int f = 0; f < 4; ++f)
                #pragma unroll
                for (int q = 0; q < 4; ++q) uacc[f][q] = 0.f;
            const uint32_t mrow = (uint32_t)(16 * wid + (lid & 15)) * 512;
            const uint32_t asel = (uint32_t)((lid >> 4) << 4);
            const uint32_t brow0 = (uint32_t)(((lid >> 4) << 3) + (lid & 7)) * 512;
            const uint32_t brow1 = brow0 + 16 * 512;
            const uint32_t bsel = (uint32_t)(((lid >> 3) & 1) << 4);
            #pragma unroll
            for (int ks = 0; ks < 16; ++ks) {
                uint32_t ca = ks * 32;
                uint32_t am[4], b0[4], b1[4];
                ldsm_x4(am, MH + SWZ5(mrow + ca + asel));
                ldsm_x4(b0, KH + SWZ5(brow0 + ca + bsel));
                ldsm_x4(b1, KH + SWZ5(brow1 + ca + bsel));
                #pragma unroll
                for (int f = 0; f < 4; ++f) {
                    const uint32_t* bh = (f < 2) ? b0 : b1;
                    int j = (f & 1) * 2;
                    mma_f16(uacc[f], am, bh[j], bh[j+1]);
                }
            }
            int i = 16 * wid + qm;
            #pragma unroll
            for (int f = 0; f < 4; ++f) {
                int lt = 8 * f + qn;
                sD[lt*128 + i]           = uacc[f][0];
                sD[(lt+1)*128 + i]       = uacc[f][1];
                sD[lt*128 + i + 8]       = uacc[f][2];
                sD[(lt+1)*128 + i + 8]   = uacc[f][3];
            }
        }
        __syncthreads();

        // ---- (e) triangular solve; rhs = fp16 K from smem tile ----
        if (tid < 128) {
            const int i = tid;
            float d[CH];
            const uint32_t coff = (uint32_t)((r0 + i) * 2);
            #pragma unroll
            for (int t = 0; t < CH; ++t) {
                uint32_t o = SWZ5((uint32_t)(t * 512) + coff);
                float rhs = __half2float(*(const __half*)(smc + KHOFF + o));
                d[t] = rhs - ct[t] * sD[t*128 + i];
            }
            #pragma unroll
            for (int s = 0; s < CH - 1; ++s)
                #pragma unroll
                for (int t = s + 1; t < CH; ++t)
                    d[t] -= sA[t*32 + s] * d[s];
            #pragma unroll
            for (int s = 0; s < CH; s += 2)
                *(uint32_t*)(smc + OFF_DT + i*80 + s*2) =
                    packh2(d[s] * wv[s], d[s+1] * wv[s+1]);
        }
        __syncthreads();

        // ---- (f) M update ----
        {
            float bc = spw[Cc];
            #pragma unroll
            for (int f = 0; f < 32; ++f)
                #pragma unroll
                for (int q = 0; q < 4; ++q) acc[f][q] *= bc;
            const uint32_t adbase = (uint32_t)(16 * wid + (lid & 15)) * 80
                                  + (uint32_t)((lid >> 4) << 4);
            const uint32_t tsel = (uint32_t)((lid >> 4) << 3) * 2;
            #pragma unroll
            for (int ks = 0; ks < 2; ++ks) {
                uint32_t ad[4];
                ldsm_x4(ad, sb + OFF_DT + adbase + ks * 32);
                uint32_t trow = (uint32_t)(ks * 16 + (lid & 15)) * 512;
                #pragma unroll
                for (int jg = 0; jg < 16; ++jg) {
                    uint32_t o = SWZ5(trow + jg * 32 + tsel);
                    uint32_t bt[4];
                    ldsm_x4t(bt, KH + o);
                    mma_f16(acc[jg*2],   ad, bt[0], bt[1]);
                    mma_f16(acc[jg*2+1], ad, bt[2], bt[3]);
                }
            }
        }

        // ---- (g) publish M fp16 ----
        if (c + 1 < NCH) {
            int r1 = 16 * wid + qm;
            #pragma unroll
            for (int f = 0; f < 32; ++f) {
                int cc = f * 8 + qn;
                *(uint32_t*)(smc + OFF_MH + SWZ5((uint32_t)(r1 * 512 + cc * 2))) =
                    packh2(acc[f][0], acc[f][1]);
                *(uint32_t*)(smc + OFF_MH + SWZ5((uint32_t)((r1 + 8) * 512 + cc * 2))) =
                    packh2(acc[f][2], acc[f][3]);
            }
        }
    }

    // ---- final: stage fp32 M, write g_M ----
    __syncthreads();
    {
        float* SF = (float*)smc;
        int r1 = 16 * wid + qm;
        #pragma unroll
        for (int f = 0; f < 32; ++f) {
            int c = f * 8 + qn;
            SF[r1*256 + c]       = acc[f][0];
            SF[r1*256 + c + 1]   = acc[f][1];
            SF[(r1+8)*256 + c]   = acc[f][2];
            SF[(r1+8)*256 + c+1] = acc[f][3];
        }
        __syncthreads();
        const float4* sp = (const float4*)SF;
        for (int q = tid; q < 128 * 64; q += 256) {
            int i = q >> 6, j4 = q & 63;
            ((float4*)(g_M + ((size_t)b * HH + r0 + i) * HH))[j4] = sp[i*64 + j4];
        }
    }
}

// ---------------- 5. readout: y = M LN(h_last) ----------------
__global__ void k_read1(const float* __restrict__ gamma, const float* __restrict__ beta_ln) {
    int b = blockIdx.x;
    int tid = threadIdx.x;
    __shared__ float hl[HH];
    __shared__ float red[8];
    float x = g_h[((size_t)b * LL + (LL - 1)) * HH + tid];
    float s = x;
    #pragma unroll
    for (int o = 16; o; o >>= 1) s += __shfl_xor_sync(0xffffffffu, s, o);
    if ((tid & 31) == 0) red[tid >> 5] = s;
    __syncthreads();
    float mu = 0.f;
    #pragma unroll
    for (int i = 0; i < 8; ++i) mu += red[i];
    mu *= (1.0f / HH);
    __syncthreads();
    float dx = x - mu;
    float v = dx * dx;
    #pragma unroll
    for (int o = 16; o; o >>= 1) v += __shfl_xor_sync(0xffffffffu, v, o);
    if ((tid & 31) == 0) red[tid >> 5] = v;
    __syncthreads();
    float var = 0.f;
    #pragma unroll
    for (int i = 0; i < 8; ++i) var += red[i];
    var *= (1.0f / HH);
    hl[tid] = dx * rsqrtf(var + 1e-5f) * gamma[tid] + beta_ln[tid];
    __syncthreads();
    int w = tid >> 5, lane = tid & 31;
    for (int i = w; i < HH; i += 8) {
        const float* Mr = g_M + ((size_t)b * HH + i) * HH;
        float acc = 0.f;
        #pragma unroll
        for (int j = lane; j < HH; j += 32) acc += Mr[j] * hl[j];
        #pragma unroll
        for (int o = 16; o; o >>= 1) acc += __shfl_xor_sync(0xffffffffu, acc, o);
        if (lane == 0) g_y[b * HH + i] = acc;
    }
}

__global__ void k_read2(const float* __restrict__ rp_W, const float* __restrict__ rp_b) {
    int b = blockIdx.x, n = threadIdx.x;
    __shared__ float ys[HH];
    ys[n] = g_y[b * HH + n];
    __syncthreads();
    float acc = rp_b[n];
    #pragma unroll 4
    for (int k = 0; k < HH; ++k) acc += ys[k] * rp_W[k * HH + n];
    g_y2[b * HH + n] = acc;
}

static constexpr int OUT_SMEM_BYTES = (HH * 128 + BB * 257) * 4;

__global__ __launch_bounds__(256) void k_out(
    const float* __restrict__ out_W, const float* __restrict__ out_b,
    float* __restrict__ out)
{
    extern __shared__ float smf[];
    float* sW  = smf;
    float* sy2 = smf + HH * 128;
    int tid = threadIdx.x;
    int n_base = blockIdx.x * 128;

    for (int idx = tid; idx < HH * 32; idx += 256) {
        int k = idx >> 5, q = idx & 31;
        *(float4*)(sW + k*128 + q*4) = *(const float4*)(out_W + (size_t)k * VV + n_base + q*4);
    }
    for (int idx = tid; idx < BB * 64; idx += 256) {
        int bb = idx >> 6, q = idx & 63;
        float4 v = *(const float4*)(g_y2 + bb * HH + q*4);
        float* d = sy2 + bb*257 + q*4;
        d[0] = v.x; d[1] = v.y; d[2] = v.z; d[3] = v.w;
    }
    __syncthreads();

    int bg = tid >> 4, ng = tid & 15;
    int b0 = bg * 4, n0 = ng * 8;
    float acc[4][8];
    #pragma unroll
    for (int r = 0; r < 4; ++r)
        #pragma unroll
        for (int c = 0; c < 8; ++c) acc[r][c] = 0.f;
    for (int k = 0; k < HH; ++k) {
        float4 w0 = *(const float4*)(sW + k*128 + n0);
        float4 w1 = *(const float4*)(sW + k*128 + n0 + 4);
        float wv[8] = {w0.x, w0.y, w0.z, w0.w, w1.x, w1.y, w1.z, w1.w};
        #pragma unroll
        for (int r = 0; r < 4; ++r) {
            float yv = sy2[(b0+r)*257 + k];
            #pragma unroll
            for (int c = 0; c < 8; ++c) acc[r][c] += yv * wv[c];
        }
    }
    #pragma unroll
    for (int r = 0; r < 4; ++r)
        #pragma unroll
        for (int c = 0; c < 8; ++c)
            out[(size_t)(b0+r) * VV + n_base + n0 + c] = acc[r][c] + out_b[n_base + n0 + c];
}

// ---------------- launch ----------------
extern "C" void kernel_launch(void* const* d_in, const int* in_sizes, int n_in,
                              void* d_out, int out_size) {
    (void)in_sizes; (void)n_in; (void)out_size;
    const int*   seq     = (const int*)  d_in[0];
    const float* embed   = (const float*)d_in[1];
    const float* W1      = (const float*)d_in[2];
    const float* b1      = (const float*)d_in[3];
    const float* W2      = (const float*)d_in[4];
    const float* b2      = (const float*)d_in[5];
    const float* gamma   = (const float*)d_in[6];
    const float* beta_ln = (const float*)d_in[7];
    const float* rp_W    = (const float*)d_in[8];
    const float* rp_b    = (const float*)d_in[9];
    const float* out_W   = (const float*)d_in[10];
    const float* out_b   = (const float*)d_in[11];
    float* out = (float*)d_out;

    cudaFuncSetAttribute(k_ffn<1>, cudaFuncAttributeMaxDynamicSharedMemorySize, FFN_SMEM);
    cudaFuncSetAttribute(k_ffn<2>, cudaFuncAttributeMaxDynamicSharedMemorySize, FFN_SMEM);
    cudaFuncSetAttribute(k_scan,   cudaFuncAttributeMaxDynamicSharedMemorySize, SCAN_SMEM_BYTES);
    cudaFuncSetAttribute(k_out,    cudaFuncAttributeMaxDynamicSharedMemorySize, OUT_SMEM_BYTES);

    k_prep<<<512, 256>>>(W1, W2);
    k_split<<<BB * LL * 32 / 256, 256>>>(seq, embed);
    k_ffn<1><<<dim3(4, BB*LL/128), 256, FFN_SMEM>>>(seq, embed, b1);
    k_ffn<2><<<dim3(2, BB*LL/128), 256, FFN_SMEM>>>(seq, embed, b2);
    k_ln<<<BB * LL / 8, 256>>>(gamma, beta_ln);
    k_scan<<<BB * 2, 256, SCAN_SMEM_BYTES>>>();
    k_read1<<<BB, HH>>>(gamma, beta_ln);
    k_read2<<<BB, HH>>>(rp_W, rp_b);
    k_out<<<VV / 128, 256, OUT_SMEM_BYTES>>>(out_W, out_b, out);
}